// round 12
// baseline (speedup 1.0000x reference)
#include <cuda_runtime.h>
#include <cstdint>

#define N_NODES 50000
#define N_EDGES 800000

typedef unsigned long long ull;

// ---------------- scratch (device globals; zero-init at load) ---------------
__device__ float g_h[N_NODES * 64];        // node features
__device__ float g_NP[N_NODES * 256];      // per-node proj, interleaved quads
__device__ float g_agg[N_NODES * 64];      // message accumulator (kept zeroed)
__device__ float g_Wcomb[41 * 384];
__device__ ulonglong2 g_WcombT2[3 * 2 * 21 * 32]; // [layer][mat][kpair][lane]
__device__ float g_bcomb[384];
__device__ float g_Wnode[3 * 64 * 256];    // per-layer node projection (interleaved)
__device__ float g_W1n[92 * 256];          // W1 @ Wnode0 (layer-0 folded)
__device__ float g_b1n[256];
__device__ float g_stats[3 * 128];         // per-layer BN sums/sumsq
// CSR machinery
__device__ int   g_src32[N_EDGES];
__device__ int   g_tgt32[N_EDGES];
__device__ int   g_deg[N_NODES];           // kept zeroed across launches
__device__ int   g_cursor[N_NODES];
__device__ int   g_srcperm[N_EDGES];
__device__ int   g_tgtperm[N_EDGES];
__device__ float g_eaperm[(size_t)N_EDGES * 48];  // stride 48 (192B rows)

// ---------------- f32x2 helpers --------------------------------------------
__device__ __forceinline__ ull fma2(ull a, ull b, ull c) {
    ull d;
    asm("fma.rn.f32x2 %0, %1, %2, %3;" : "=l"(d) : "l"(a), "l"(b), "l"(c));
    return d;
}
__device__ __forceinline__ ull dup2(float v) {
    ull d; unsigned u = __float_as_uint(v);
    asm("mov.b64 %0, {%1, %2};" : "=l"(d) : "r"(u), "r"(u));
    return d;
}
__device__ __forceinline__ float2 unpack2(ull v) {
    unsigned lo, hi;
    asm("mov.b64 {%0, %1}, %2;" : "=r"(lo), "=r"(hi) : "l"(v));
    return make_float2(__uint_as_float(lo), __uint_as_float(hi));
}
__device__ __forceinline__ void red2(float* p, float a, float b) {
    asm volatile("red.global.add.v2.f32 [%0], {%1, %2};" :: "l"(p), "f"(a), "f"(b) : "memory");
}
__device__ __forceinline__ float sigmoidf_(float x) {
    return __fdividef(1.f, 1.f + __expf(-x));
}
__device__ __forceinline__ float softplusf_(float x) {
    return fmaxf(x, 0.f) + __logf(1.f + __expf(-fabsf(x)));
}

// ---------------- launch 1: detect dtype, convert, histogram, zero stats ----
__global__ void __launch_bounds__(256) convert_hist(const void* __restrict__ raw) {
    __shared__ int s_is64;
    const int gt = blockIdx.x * 256 + threadIdx.x;
    if (gt < 3 * 128) g_stats[gt] = 0.f;
    if (threadIdx.x == 0) {
        const int* r32 = (const int*)raw;
        int is64 = 1;
        for (int i = 0; i < 64; i++)
            if (r32[2 * i + 1] != 0) { is64 = 0; break; }
        s_is64 = is64;
    }
    __syncthreads();
    const int e = gt;
    if (e >= N_EDGES) return;
    int s, t;
    if (s_is64) {
        s = (int)((const long long*)raw)[e];
        t = (int)((const long long*)raw)[N_EDGES + e];
    } else {
        s = ((const int*)raw)[e];
        t = ((const int*)raw)[N_EDGES + e];
    }
    s = min(max(s, 0), N_NODES - 1);
    t = min(max(t, 0), N_NODES - 1);
    g_src32[e] = s;
    g_tgt32[e] = t;
    atomicAdd(&g_deg[t], 1);
}

// ---------------- launch 2: scan + all weight precombination (1 block) ------
__global__ void __launch_bounds__(512) scan_combine(
    const float* __restrict__ Wf, const float* __restrict__ bf,
    const float* __restrict__ Ws, const float* __restrict__ bs,
    const float* __restrict__ W2, const float* __restrict__ b2,
    const float* __restrict__ W1, const float* __restrict__ b1) {
    __shared__ int ssum[512];
    const int tid = threadIdx.x;

    const int base = tid * 98;
    const int lim = min(base + 98, N_NODES);
    int s = 0;
    for (int i = base; i < lim; i++) s += g_deg[i];
    ssum[tid] = s;
    __syncthreads();
    for (int off = 1; off < 512; off <<= 1) {
        int v = (tid >= off) ? ssum[tid - off] : 0;
        __syncthreads();
        ssum[tid] += v;
        __syncthreads();
    }
    int run = ssum[tid] - s;
    for (int i = base; i < lim; i++) {
        g_cursor[i] = run;
        run += g_deg[i];
    }

    if (tid < 384) {
        const int c = tid;
        const int i = c >> 7;
        const int r = c & 127;
        const bool isF = r < 64;
        const int j = r & 63;
        const float* WB = isF ? Wf : Ws;
        const float* bB = isF ? bf : bs;
        float wc[64];
#pragma unroll
        for (int k = 0; k < 64; k++) wc[k] = WB[i * 12288 + (128 + k) * 64 + j];
        float bacc = bB[i * 64 + j];
#pragma unroll
        for (int k = 0; k < 64; k++) bacc += b2[k] * wc[k];
        g_bcomb[c] = bacc;
        for (int a = 0; a < 41; a++) {
            float acc = 0.f;
#pragma unroll
            for (int k = 0; k < 64; k++) acc += W2[a * 64 + k] * wc[k];
            g_Wcomb[a * 384 + c] = acc;
        }
    }
    // Wnode interleaved: row = [T-block 128][S-block 128];
    // quad r4: sub0,1 = gate cols(2r4,2r4+1), sub2,3 = core cols
    for (int idx = tid; idx < 3 * 64 * 256; idx += 512) {
        int l = idx >> 14;
        int rem = idx & 16383;
        int k = rem >> 8;
        int cc = rem & 255;
        int b = cc >> 7;
        int r4 = (cc & 127) >> 2;
        int sub = cc & 3;
        const float* S = (sub < 2) ? Wf : Ws;
        int jj = 2 * r4 + (sub & 1);
        int row = k + (b ? 64 : 0);
        g_Wnode[idx] = S[l * 12288 + row * 64 + jj];
    }
    __syncthreads();

    for (int idx = tid; idx < 3 * 2 * 21 * 32; idx += 512) {
        const int lane = idx & 31;
        const int kk = (idx >> 5) % 21;
        const int mat = (idx / (21 * 32)) & 1;
        const int lay = idx / (2 * 21 * 32);
        const int colbase = lay * 128 + mat * 64 + 2 * lane;
        const int k0 = 2 * kk, k1 = 2 * kk + 1;
        ulonglong2 v;
        {
            unsigned lo = __float_as_uint(g_Wcomb[k0 * 384 + colbase]);
            unsigned hi = __float_as_uint(g_Wcomb[k0 * 384 + colbase + 1]);
            v.x = ((ull)hi << 32) | lo;
        }
        if (k1 < 41) {
            unsigned lo = __float_as_uint(g_Wcomb[k1 * 384 + colbase]);
            unsigned hi = __float_as_uint(g_Wcomb[k1 * 384 + colbase + 1]);
            v.y = ((ull)hi << 32) | lo;
        } else {
            v.y = 0ull;
        }
        g_WcombT2[idx] = v;
    }
    for (int idx = tid; idx < 92 * 256; idx += 512) {
        int a = idx >> 8, cc = idx & 255;
        float acc = 0.f;
#pragma unroll 8
        for (int k = 0; k < 64; k++) acc += W1[a * 64 + k] * g_Wnode[k * 256 + cc];
        g_W1n[idx] = acc;
    }
    if (tid < 256) {
        float acc = 0.f;
#pragma unroll 8
        for (int k = 0; k < 64; k++) acc += b1[k] * g_Wnode[k * 256 + tid];
        g_b1n[tid] = acc;
    }
}

// ---------------- launch 3: scatter (standalone, low regs, high occ) --------
__global__ void __launch_bounds__(256) scatter_permute(const float* __restrict__ ea) {
    const int w = threadIdx.x >> 5, lane = threadIdx.x & 31;
    const int eb = blockIdx.x * 256 + w * 32;
    const int e = eb + lane;
    const int tg = g_tgt32[e];
    const int pos = atomicAdd(&g_cursor[tg], 1);
    g_srcperm[pos] = g_src32[e];
    g_tgtperm[pos] = tg;
#pragma unroll 8
    for (int j = 0; j < 32; j++) {
        int pe = __shfl_sync(0xffffffffu, pos, j);
        const float* s = ea + (size_t)(eb + j) * 41;
        float* d = g_eaperm + (size_t)pe * 48;
        d[lane] = s[lane];
        if (lane < 16) {
            int c = 32 + lane;
            d[c] = (c < 41) ? s[c] : 0.f;
        }
    }
}

// ---------------- h0 = x @ W1 + b1 (8 rows / 32 thr) ------------------------
__global__ void __launch_bounds__(32) h0_gemm(const float* __restrict__ x,
                                              const float* __restrict__ W1,
                                              const float* __restrict__ b1) {
    __shared__ __align__(16) ull a_s[8][92];
    const int tid = threadIdx.x;
    const int row0 = blockIdx.x * 8;
    for (int idx = tid; idx < 8 * 92; idx += 32) {
        int r = idx / 92, k = idx - r * 92;
        a_s[r][k] = dup2(x[(size_t)row0 * 92 + idx]);
    }
    __syncwarp();
    const int c = tid * 2;
    ull acc[8];
#pragma unroll
    for (int r = 0; r < 8; r++) acc[r] = 0ull;
#pragma unroll 2
    for (int kk = 0; kk < 46; kk++) {
        ull w0 = *(const ull*)(W1 + (2 * kk) * 64 + c);
        ull w1v = *(const ull*)(W1 + (2 * kk + 1) * 64 + c);
#pragma unroll
        for (int r = 0; r < 8; r++) {
            ulonglong2 av = *(const ulonglong2*)&a_s[r][2 * kk];
            acc[r] = fma2(w0, av.x, acc[r]);
            acc[r] = fma2(w1v, av.y, acc[r]);
        }
    }
    float2 b = *(const float2*)(b1 + c);
#pragma unroll
    for (int r = 0; r < 8; r++) {
        float2 v = unpack2(acc[r]);
        v.x += b.x; v.y += b.y;
        *(float2*)&g_h[(size_t)(row0 + r) * 64 + c] = v;
    }
}

// ---------------- NP0 = x @ W1n + b1n (8 rows / 64 thr) ---------------------
__global__ void __launch_bounds__(64) np0_gemm(const float* __restrict__ x) {
    __shared__ __align__(16) ull b_s[8][92];
    const int tid = threadIdx.x;
    const int row0 = blockIdx.x * 8;
    for (int idx = tid; idx < 8 * 92; idx += 64) {
        int r = idx / 92, k = idx - r * 92;
        b_s[r][k] = dup2(x[(size_t)row0 * 92 + idx]);
    }
    __syncthreads();
    const int c = tid * 4;
    ull acc0[8], acc1[8];
#pragma unroll
    for (int r = 0; r < 8; r++) { acc0[r] = 0ull; acc1[r] = 0ull; }
#pragma unroll 2
    for (int kk = 0; kk < 46; kk++) {
        ulonglong2 w0 = *(const ulonglong2*)(g_W1n + (2 * kk) * 256 + c);
        ulonglong2 w1 = *(const ulonglong2*)(g_W1n + (2 * kk + 1) * 256 + c);
#pragma unroll
        for (int r = 0; r < 8; r++) {
            ulonglong2 av = *(const ulonglong2*)&b_s[r][2 * kk];
            acc0[r] = fma2(w0.x, av.x, acc0[r]);
            acc1[r] = fma2(w0.y, av.x, acc1[r]);
            acc0[r] = fma2(w1.x, av.y, acc0[r]);
            acc1[r] = fma2(w1.y, av.y, acc1[r]);
        }
    }
    float2 ba = *(const float2*)(g_b1n + c);
    float2 bb = *(const float2*)(g_b1n + c + 2);
#pragma unroll
    for (int r = 0; r < 8; r++) {
        float2 v0 = unpack2(acc0[r]);
        float2 v1 = unpack2(acc1[r]);
        float4 o = make_float4(v0.x + ba.x, v0.y + ba.y, v1.x + bb.x, v1.y + bb.y);
        *(float4*)&g_NP[(size_t)(row0 + r) * 256 + c] = o;
    }
}

// ---------------- NP GEMM for layers 1,2 ------------------------------------
__global__ void __launch_bounds__(64) np_gemm(const float* __restrict__ A,
                                              const float* __restrict__ W) {
    __shared__ __align__(16) ull a_s[8][64];
    const int tid = threadIdx.x;
    const int row0 = blockIdx.x * 8;
    for (int idx = tid; idx < 8 * 64; idx += 64) {
        int r = idx >> 6, k = idx & 63;
        a_s[r][k] = dup2(A[(size_t)row0 * 64 + idx]);
    }
    __syncthreads();
    const int c = tid * 4;
    ull acc0[8], acc1[8];
#pragma unroll
    for (int r = 0; r < 8; r++) { acc0[r] = 0ull; acc1[r] = 0ull; }
#pragma unroll 2
    for (int kk = 0; kk < 32; kk++) {
        ulonglong2 w0 = *(const ulonglong2*)(W + (2 * kk) * 256 + c);
        ulonglong2 w1 = *(const ulonglong2*)(W + (2 * kk + 1) * 256 + c);
#pragma unroll
        for (int r = 0; r < 8; r++) {
            ulonglong2 av = *(const ulonglong2*)&a_s[r][2 * kk];
            acc0[r] = fma2(w0.x, av.x, acc0[r]);
            acc1[r] = fma2(w0.y, av.x, acc1[r]);
            acc0[r] = fma2(w1.x, av.y, acc0[r]);
            acc1[r] = fma2(w1.y, av.y, acc1[r]);
        }
    }
#pragma unroll
    for (int r = 0; r < 8; r++) {
        float2 v0 = unpack2(acc0[r]);
        float2 v1 = unpack2(acc1[r]);
        float4 o = make_float4(v0.x, v0.y, v1.x, v1.y);
        *(float4*)&g_NP[(size_t)(row0 + r) * 256 + c] = o;
    }
}

// ---------------- edge kernel: acc round-trip through smem -> low regs ------
__global__ void __launch_bounds__(128) edge_kernel(int layer) {
    __shared__ __align__(16) ull ea_s[4][8][48];
    __shared__ __align__(16) ull acc_s[4][8][64];  // [warp][edge][gate32|core32]
    __shared__ int src_s[4][8], tgt_s[4][8];
    const int w = threadIdx.x >> 5, lane = threadIdx.x & 31;
    const int e0 = (blockIdx.x * 4 + w) * 8;
    const int cg = 2 * lane;

    if (lane < 8)       src_s[w][lane] = g_srcperm[e0 + lane];
    else if (lane < 16) tgt_s[w][lane - 8] = g_tgtperm[e0 + lane - 8];

#pragma unroll
    for (int j = 0; j < 3; j++) {
        int idx = lane + j * 32;
        int r = idx / 12, c4 = idx - r * 12;
        float4 v = *(const float4*)(g_eaperm + (size_t)(e0 + r) * 48 + 4 * c4);
        ulonglong2 p0, p1;
        p0.x = dup2(v.x); p0.y = dup2(v.y);
        p1.x = dup2(v.z); p1.y = dup2(v.w);
        *(ulonglong2*)&ea_s[w][r][4 * c4]     = p0;
        *(ulonglong2*)&ea_s[w][r][4 * c4 + 2] = p1;
    }
    __syncwarp();

    // ---- phase 1: GEMM; accumulators die into smem at the end ----
    {
        const ulonglong2* WG = g_WcombT2 + (size_t)(layer * 2 + 0) * 21 * 32 + lane;
        const ulonglong2* WC = g_WcombT2 + (size_t)(layer * 2 + 1) * 21 * 32 + lane;

        ull accG[8], accC[8];
#pragma unroll
        for (int r = 0; r < 8; r++) { accG[r] = 0ull; accC[r] = 0ull; }

#pragma unroll
        for (int kk = 0; kk < 21; kk++) {
            ulonglong2 wg = WG[kk * 32];
            ulonglong2 wc = WC[kk * 32];
#pragma unroll
            for (int r = 0; r < 8; r++) {
                ulonglong2 av = *(const ulonglong2*)&ea_s[w][r][2 * kk];
                accG[r] = fma2(wg.x, av.x, accG[r]);
                accG[r] = fma2(wg.y, av.y, accG[r]);
                accC[r] = fma2(wc.x, av.x, accC[r]);
                accC[r] = fma2(wc.y, av.y, accC[r]);
            }
        }
#pragma unroll
        for (int r = 0; r < 8; r++) {
            acc_s[w][r][lane]      = accG[r];   // lane-private slot: no sync needed
            acc_s[w][r][32 + lane] = accC[r];
        }
    }

    // ---- phase 2: epilogue; prefetch all 16 gathers (regs freed by phase 1) -
    float4 s4[8], t4[8];
#pragma unroll
    for (int r = 0; r < 8; r++) {
        s4[r] = *(const float4*)(g_NP + (size_t)src_s[w][r] * 256 + 128 + 4 * lane);
        t4[r] = *(const float4*)(g_NP + (size_t)tgt_s[w][r] * 256 + 4 * lane);
    }

    const float2 bg = *(const float2*)(g_bcomb + layer * 128 + cg);
    const float2 bc = *(const float2*)(g_bcomb + layer * 128 + 64 + cg);

    int cur = tgt_s[w][0];
    float2 agg = make_float2(0.f, 0.f);

#pragma unroll
    for (int r = 0; r < 8; r++) {
        const int tn = tgt_s[w][r];
        if (tn != cur) {                 // warp-uniform
            red2(g_agg + (size_t)cur * 64 + cg, agg.x, agg.y);
            cur = tn;
            agg.x = 0.f; agg.y = 0.f;
        }
        float2 g = unpack2(acc_s[w][r][lane]);
        float2 cp = unpack2(acc_s[w][r][32 + lane]);
        g.x  += bg.x + t4[r].x + s4[r].x;   g.y  += bg.y + t4[r].y + s4[r].y;
        cp.x += bc.x + t4[r].z + s4[r].z;   cp.y += bc.y + t4[r].w + s4[r].w;
        agg.x += sigmoidf_(g.x) * softplusf_(cp.x);
        agg.y += sigmoidf_(g.y) * softplusf_(cp.y);
    }
    red2(g_agg + (size_t)cur * 64 + cg, agg.x, agg.y);
}

// ---------------- residual + BN statistics (+ agg re-zero) ------------------
__global__ void __launch_bounds__(256) resid_stats(int layer) {
    const int col = threadIdx.x & 63;
    const int rgrp = threadIdx.x >> 6;
    float s = 0.f, q = 0.f;
    for (int row = blockIdx.x * 4 + rgrp; row < N_NODES; row += gridDim.x * 4) {
        const int idx = row * 64 + col;
        float t = g_h[idx] + g_agg[idx];
        g_h[idx] = t;
        g_agg[idx] = 0.f;                    // ready for next layer / replay
        s += t; q += t * t;
    }
    atomicAdd(&g_stats[layer * 128 + col], s);
    atomicAdd(&g_stats[layer * 128 + 64 + col], q);
}

// ---------------- BN normalize (+relu); final: zero deg ---------------------
__global__ void __launch_bounds__(256) bn_kernel(const float* __restrict__ gamma,
                                                 const float* __restrict__ beta,
                                                 int layer, float* __restrict__ dst,
                                                 int do_relu, int final_) {
    const int i = blockIdx.x * blockDim.x + threadIdx.x;  // exact grid: 3.2M
    const int col = i & 63;
    const float invN = 1.f / (float)N_NODES;
    float mean = g_stats[layer * 128 + col] * invN;
    float var = g_stats[layer * 128 + 64 + col] * invN - mean * mean;
    float inv = rsqrtf(var + 1e-5f);
    float v = (g_h[i] - mean) * inv * gamma[layer * 64 + col] + beta[layer * 64 + col];
    if (do_relu) v = fmaxf(v, 0.f);
    dst[i] = v;
    if (final_ && i < N_NODES) g_deg[i] = 0;
}

// ---------------- launch ----------------------------------------------------
extern "C" void kernel_launch(void* const* d_in, const int* in_sizes, int n_in,
                              void* d_out, int out_size) {
    const float* x   = (const float*)d_in[0];
    const float* ea  = (const float*)d_in[1];
    const void*  ei  = d_in[2];
    const float* W1  = (const float*)d_in[3];
    const float* b1  = (const float*)d_in[4];
    const float* W2  = (const float*)d_in[5];
    const float* b2  = (const float*)d_in[6];
    const float* Wf  = (const float*)d_in[7];
    const float* bf  = (const float*)d_in[8];
    const float* Ws  = (const float*)d_in[9];
    const float* bs  = (const float*)d_in[10];
    const float* gamma = (const float*)d_in[11];
    const float* beta  = (const float*)d_in[12];
    float* out = (float*)d_out;

    void *ph, *pwn;
    cudaGetSymbolAddress(&ph, g_h);
    cudaGetSymbolAddress(&pwn, g_Wnode);
    float* hbuf  = (float*)ph;
    float* wnode = (float*)pwn;

    convert_hist<<<(N_EDGES + 255) / 256, 256>>>(ei);
    scan_combine<<<1, 512>>>(Wf, bf, Ws, bs, W2, b2, W1, b1);
    scatter_permute<<<N_EDGES / 256, 256>>>(ea);
    h0_gemm<<<N_NODES / 8, 32>>>(x, W1, b1);
    np0_gemm<<<N_NODES / 8, 64>>>(x);

    for (int l = 0; l < 3; l++) {
        if (l > 0) np_gemm<<<N_NODES / 8, 64>>>(hbuf, wnode + l * 16384);
        edge_kernel<<<N_EDGES / 32, 128>>>(l);
        resid_stats<<<1024, 256>>>(l);
        const int last = (l == 2);
        bn_kernel<<<(N_NODES * 64) / 256, 256>>>(gamma, beta, l,
                                                 last ? out : hbuf,
                                                 last ? 0 : 1, last);
    }
}

// round 13
// speedup vs baseline: 1.0077x; 1.0077x over previous
#include <cuda_runtime.h>
#include <cstdint>

#define N_NODES 50000
#define N_EDGES 800000

typedef unsigned long long ull;

// ---------------- scratch (device globals; zero-init at load) ---------------
__device__ float g_h[N_NODES * 64];        // node features
__device__ float g_NP[N_NODES * 256];      // per-node proj: [f_t|f_s|s_t|s_s]
__device__ float g_agg[N_NODES * 64];      // message accumulator (kept zeroed)
__device__ float g_Wcomb[41 * 384];
__device__ ull   g_WcombT[3 * 2 * 32 * 42];// lane-major: [layer][mat][lane][k]
__device__ float g_bcomb[384];
__device__ float g_Wnode[3 * 64 * 256];    // per-layer node projection (part layout)
__device__ float g_W1n[92 * 256];          // W1 @ Wnode0 (layer-0 folded)
__device__ float g_b1n[256];
__device__ float g_stats[3 * 128];         // per-layer BN sums/sumsq
// CSR machinery
__device__ int   g_src32[N_EDGES];
__device__ int   g_tgt32[N_EDGES];
__device__ int   g_deg[N_NODES];           // kept zeroed across launches
__device__ int   g_cursor[N_NODES];
__device__ int   g_srcperm[N_EDGES];
__device__ int   g_tgtperm[N_EDGES];
__device__ float g_eaperm[(size_t)N_EDGES * 48];  // stride 48 (192B rows)

// ---------------- f32x2 helpers --------------------------------------------
__device__ __forceinline__ ull fma2(ull a, ull b, ull c) {
    ull d;
    asm("fma.rn.f32x2 %0, %1, %2, %3;" : "=l"(d) : "l"(a), "l"(b), "l"(c));
    return d;
}
__device__ __forceinline__ ull dup2(float v) {
    ull d; unsigned u = __float_as_uint(v);
    asm("mov.b64 %0, {%1, %2};" : "=l"(d) : "r"(u), "r"(u));
    return d;
}
__device__ __forceinline__ float2 unpack2(ull v) {
    unsigned lo, hi;
    asm("mov.b64 {%0, %1}, %2;" : "=r"(lo), "=r"(hi) : "l"(v));
    return make_float2(__uint_as_float(lo), __uint_as_float(hi));
}
__device__ __forceinline__ void red2(float* p, float a, float b) {
    asm volatile("red.global.add.v2.f32 [%0], {%1, %2};" :: "l"(p), "f"(a), "f"(b) : "memory");
}
__device__ __forceinline__ float sigmoidf_(float x) {
    return __fdividef(1.f, 1.f + __expf(-x));
}
__device__ __forceinline__ float softplusf_(float x) {
    return fmaxf(x, 0.f) + __logf(1.f + __expf(-fabsf(x)));
}

// ---------------- launch 1: detect dtype, convert, histogram, zero stats ----
__global__ void __launch_bounds__(256) convert_hist(const void* __restrict__ raw) {
    __shared__ int s_is64;
    const int gt = blockIdx.x * 256 + threadIdx.x;
    if (gt < 3 * 128) g_stats[gt] = 0.f;
    if (threadIdx.x == 0) {
        const int* r32 = (const int*)raw;
        int is64 = 1;
        for (int i = 0; i < 64; i++)
            if (r32[2 * i + 1] != 0) { is64 = 0; break; }
        s_is64 = is64;
    }
    __syncthreads();
    const int e = gt;
    if (e >= N_EDGES) return;
    int s, t;
    if (s_is64) {
        s = (int)((const long long*)raw)[e];
        t = (int)((const long long*)raw)[N_EDGES + e];
    } else {
        s = ((const int*)raw)[e];
        t = ((const int*)raw)[N_EDGES + e];
    }
    s = min(max(s, 0), N_NODES - 1);
    t = min(max(t, 0), N_NODES - 1);
    g_src32[e] = s;
    g_tgt32[e] = t;
    atomicAdd(&g_deg[t], 1);
}

// ---------------- launch 2: scan + all weight precombination (1 block) ------
__global__ void __launch_bounds__(512) scan_combine(
    const float* __restrict__ Wf, const float* __restrict__ bf,
    const float* __restrict__ Ws, const float* __restrict__ bs,
    const float* __restrict__ W2, const float* __restrict__ b2,
    const float* __restrict__ W1, const float* __restrict__ b1) {
    __shared__ int ssum[512];
    const int tid = threadIdx.x;

    // exclusive scan of degrees -> g_cursor
    const int base = tid * 98;
    const int lim = min(base + 98, N_NODES);
    int s = 0;
    for (int i = base; i < lim; i++) s += g_deg[i];
    ssum[tid] = s;
    __syncthreads();
    for (int off = 1; off < 512; off <<= 1) {
        int v = (tid >= off) ? ssum[tid - off] : 0;
        __syncthreads();
        ssum[tid] += v;
        __syncthreads();
    }
    int run = ssum[tid] - s;
    for (int i = base; i < lim; i++) {
        g_cursor[i] = run;
        run += g_deg[i];
    }

    if (tid < 384) {
        const int c = tid;
        const int i = c >> 7;
        const int r = c & 127;
        const bool isF = r < 64;
        const int j = r & 63;
        const float* WB = isF ? Wf : Ws;
        const float* bB = isF ? bf : bs;
        float wc[64];
#pragma unroll
        for (int k = 0; k < 64; k++) wc[k] = WB[i * 12288 + (128 + k) * 64 + j];
        float bacc = bB[i * 64 + j];
#pragma unroll
        for (int k = 0; k < 64; k++) bacc += b2[k] * wc[k];
        g_bcomb[c] = bacc;
        for (int a = 0; a < 41; a++) {
            float acc = 0.f;
#pragma unroll
            for (int k = 0; k < 64; k++) acc += W2[a * 64 + k] * wc[k];
            g_Wcomb[a * 384 + c] = acc;
        }
    }
    // Wnode PART layout: col cc -> part = cc>>6 (0:f_t 1:f_s 2:s_t 3:s_s), jj = cc&63
    for (int idx = tid; idx < 3 * 64 * 256; idx += 512) {
        int l = idx >> 14;
        int rem = idx & 16383;
        int k = rem >> 8;
        int cc = rem & 255;
        int part = cc >> 6;
        int jj = cc & 63;
        const float* S = (part < 2) ? Wf : Ws;
        int row = k + ((part & 1) ? 64 : 0);
        g_Wnode[idx] = S[l * 12288 + row * 64 + jj];
    }
    __syncthreads();

    // lane-major transposed weights (R5 layout): [((layer*2+mat)*32+lane)*42 + k]
    for (int idx = tid; idx < 3 * 2 * 32 * 42; idx += 512) {
        int k = idx % 42;
        int rest = idx / 42;
        int lanep = rest & 31;
        rest >>= 5;
        int mat = rest & 1;
        int lay = rest >> 1;
        ull v = 0ull;
        if (k < 41) {
            unsigned lo = __float_as_uint(g_Wcomb[k * 384 + lay * 128 + mat * 64 + 2 * lanep]);
            unsigned hi = __float_as_uint(g_Wcomb[k * 384 + lay * 128 + mat * 64 + 2 * lanep + 1]);
            v = ((ull)hi << 32) | lo;
        }
        g_WcombT[idx] = v;
    }
    // W1n = W1 @ Wnode0 (part layout carried through)
    for (int idx = tid; idx < 92 * 256; idx += 512) {
        int a = idx >> 8, cc = idx & 255;
        float acc = 0.f;
#pragma unroll 8
        for (int k = 0; k < 64; k++) acc += W1[a * 64 + k] * g_Wnode[k * 256 + cc];
        g_W1n[idx] = acc;
    }
    if (tid < 256) {
        float acc = 0.f;
#pragma unroll 8
        for (int k = 0; k < 64; k++) acc += b1[k] * g_Wnode[k * 256 + tid];
        g_b1n[tid] = acc;
    }
}

// ---------------- launch 3: scatter ----------------------------------------
__global__ void __launch_bounds__(256) scatter_permute(const float* __restrict__ ea) {
    const int w = threadIdx.x >> 5, lane = threadIdx.x & 31;
    const int eb = blockIdx.x * 256 + w * 32;
    const int e = eb + lane;
    const int tg = g_tgt32[e];
    const int pos = atomicAdd(&g_cursor[tg], 1);
    g_srcperm[pos] = g_src32[e];
    g_tgtperm[pos] = tg;
#pragma unroll 8
    for (int j = 0; j < 32; j++) {
        int pe = __shfl_sync(0xffffffffu, pos, j);
        const float* s = ea + (size_t)(eb + j) * 41;
        float* d = g_eaperm + (size_t)pe * 48;
        d[lane] = s[lane];
        if (lane < 16) {
            int c = 32 + lane;
            d[c] = (c < 41) ? s[c] : 0.f;
        }
    }
}

// ---------------- h0 = x @ W1 + b1 (8 rows / 32 thr) ------------------------
__global__ void __launch_bounds__(32) h0_gemm(const float* __restrict__ x,
                                              const float* __restrict__ W1,
                                              const float* __restrict__ b1) {
    __shared__ __align__(16) ull a_s[8][92];
    const int tid = threadIdx.x;
    const int row0 = blockIdx.x * 8;
    for (int idx = tid; idx < 8 * 92; idx += 32) {
        int r = idx / 92, k = idx - r * 92;
        a_s[r][k] = dup2(x[(size_t)row0 * 92 + idx]);
    }
    __syncwarp();
    const int c = tid * 2;
    ull acc[8];
#pragma unroll
    for (int r = 0; r < 8; r++) acc[r] = 0ull;
#pragma unroll 2
    for (int kk = 0; kk < 46; kk++) {
        ull w0 = *(const ull*)(W1 + (2 * kk) * 64 + c);
        ull w1v = *(const ull*)(W1 + (2 * kk + 1) * 64 + c);
#pragma unroll
        for (int r = 0; r < 8; r++) {
            ulonglong2 av = *(const ulonglong2*)&a_s[r][2 * kk];
            acc[r] = fma2(w0, av.x, acc[r]);
            acc[r] = fma2(w1v, av.y, acc[r]);
        }
    }
    float2 b = *(const float2*)(b1 + c);
#pragma unroll
    for (int r = 0; r < 8; r++) {
        float2 v = unpack2(acc[r]);
        v.x += b.x; v.y += b.y;
        *(float2*)&g_h[(size_t)(row0 + r) * 64 + c] = v;
    }
}

// ---------------- NP0 = x @ W1n + b1n (8 rows / 64 thr) ---------------------
__global__ void __launch_bounds__(64) np0_gemm(const float* __restrict__ x) {
    __shared__ __align__(16) ull b_s[8][92];
    const int tid = threadIdx.x;
    const int row0 = blockIdx.x * 8;
    for (int idx = tid; idx < 8 * 92; idx += 64) {
        int r = idx / 92, k = idx - r * 92;
        b_s[r][k] = dup2(x[(size_t)row0 * 92 + idx]);
    }
    __syncthreads();
    const int c = tid * 4;
    ull acc0[8], acc1[8];
#pragma unroll
    for (int r = 0; r < 8; r++) { acc0[r] = 0ull; acc1[r] = 0ull; }
#pragma unroll 2
    for (int kk = 0; kk < 46; kk++) {
        ulonglong2 w0 = *(const ulonglong2*)(g_W1n + (2 * kk) * 256 + c);
        ulonglong2 w1 = *(const ulonglong2*)(g_W1n + (2 * kk + 1) * 256 + c);
#pragma unroll
        for (int r = 0; r < 8; r++) {
            ulonglong2 av = *(const ulonglong2*)&b_s[r][2 * kk];
            acc0[r] = fma2(w0.x, av.x, acc0[r]);
            acc1[r] = fma2(w0.y, av.x, acc1[r]);
            acc0[r] = fma2(w1.x, av.y, acc0[r]);
            acc1[r] = fma2(w1.y, av.y, acc1[r]);
        }
    }
    float2 ba = *(const float2*)(g_b1n + c);
    float2 bb = *(const float2*)(g_b1n + c + 2);
#pragma unroll
    for (int r = 0; r < 8; r++) {
        float2 v0 = unpack2(acc0[r]);
        float2 v1 = unpack2(acc1[r]);
        float4 o = make_float4(v0.x + ba.x, v0.y + ba.y, v1.x + bb.x, v1.y + bb.y);
        *(float4*)&g_NP[(size_t)(row0 + r) * 256 + c] = o;
    }
}

// ---------------- NP GEMM for layers 1,2 ------------------------------------
__global__ void __launch_bounds__(64) np_gemm(const float* __restrict__ A,
                                              const float* __restrict__ W) {
    __shared__ __align__(16) ull a_s[8][64];
    const int tid = threadIdx.x;
    const int row0 = blockIdx.x * 8;
    for (int idx = tid; idx < 8 * 64; idx += 64) {
        int r = idx >> 6, k = idx & 63;
        a_s[r][k] = dup2(A[(size_t)row0 * 64 + idx]);
    }
    __syncthreads();
    const int c = tid * 4;
    ull acc0[8], acc1[8];
#pragma unroll
    for (int r = 0; r < 8; r++) { acc0[r] = 0ull; acc1[r] = 0ull; }
#pragma unroll 2
    for (int kk = 0; kk < 32; kk++) {
        ulonglong2 w0 = *(const ulonglong2*)(W + (2 * kk) * 256 + c);
        ulonglong2 w1 = *(const ulonglong2*)(W + (2 * kk + 1) * 256 + c);
#pragma unroll
        for (int r = 0; r < 8; r++) {
            ulonglong2 av = *(const ulonglong2*)&a_s[r][2 * kk];
            acc0[r] = fma2(w0.x, av.x, acc0[r]);
            acc1[r] = fma2(w0.y, av.x, acc1[r]);
            acc0[r] = fma2(w1.x, av.y, acc0[r]);
            acc1[r] = fma2(w1.y, av.y, acc1[r]);
        }
    }
#pragma unroll
    for (int r = 0; r < 8; r++) {
        float2 v0 = unpack2(acc0[r]);
        float2 v1 = unpack2(acc1[r]);
        float4 o = make_float4(v0.x, v0.y, v1.x, v1.y);
        *(float4*)&g_NP[(size_t)(row0 + r) * 256 + c] = o;
    }
}

// ---------------- edge kernel: R5-exact (best known: 1272us total) ----------
__global__ void __launch_bounds__(128) edge_kernel(int layer) {
    __shared__ __align__(16) ull ea_s[4][8][48];
    __shared__ int src_s[4][8], tgt_s[4][8];
    const int w = threadIdx.x >> 5, lane = threadIdx.x & 31;
    const int e0 = (blockIdx.x * 4 + w) * 8;
    const int cg = 2 * lane;

    if (lane < 8)       src_s[w][lane] = g_srcperm[e0 + lane];
    else if (lane < 16) tgt_s[w][lane - 8] = g_tgtperm[e0 + lane - 8];

    // stage 8 rows x 48 floats = 96 float4 (aligned, 192B rows)
#pragma unroll
    for (int j = 0; j < 3; j++) {
        int idx = lane + j * 32;
        int r = idx / 12, c4 = idx - r * 12;
        float4 v = *(const float4*)(g_eaperm + (size_t)(e0 + r) * 48 + 4 * c4);
        ulonglong2 p0, p1;
        p0.x = dup2(v.x); p0.y = dup2(v.y);
        p1.x = dup2(v.z); p1.y = dup2(v.w);
        *(ulonglong2*)&ea_s[w][r][4 * c4]     = p0;
        *(ulonglong2*)&ea_s[w][r][4 * c4 + 2] = p1;
    }
    __syncwarp();

    const ull* WG = g_WcombT + ((size_t)(layer * 2 + 0) * 32 + lane) * 42;
    const ull* WC = g_WcombT + ((size_t)(layer * 2 + 1) * 32 + lane) * 42;

    ull accG[8], accC[8];
#pragma unroll
    for (int r = 0; r < 8; r++) { accG[r] = 0ull; accC[r] = 0ull; }

#pragma unroll
    for (int kk = 0; kk < 21; kk++) {
        ulonglong2 wg = *(const ulonglong2*)(WG + 2 * kk);
        ulonglong2 wc = *(const ulonglong2*)(WC + 2 * kk);
#pragma unroll
        for (int r = 0; r < 8; r++) {
            ulonglong2 av = *(const ulonglong2*)&ea_s[w][r][2 * kk];
            accG[r] = fma2(wg.x, av.x, accG[r]);
            accG[r] = fma2(wg.y, av.y, accG[r]);
            accC[r] = fma2(wc.x, av.x, accC[r]);
            accC[r] = fma2(wc.y, av.y, accC[r]);
        }
    }

    // prefetch all 8 source gathers (16 independent LDG.64 in flight)
    float2 fs[8], ss[8];
#pragma unroll
    for (int r = 0; r < 8; r++) {
        const float* NPs = g_NP + (size_t)src_s[w][r] * 256;
        fs[r] = *(const float2*)(NPs + 64 + cg);
        ss[r] = *(const float2*)(NPs + 192 + cg);
    }

    const float2 bg = *(const float2*)(g_bcomb + layer * 128 + cg);
    const float2 bc = *(const float2*)(g_bcomb + layer * 128 + 64 + cg);

    int cur = tgt_s[w][0];
    const float* NPc = g_NP + (size_t)cur * 256;
    float2 ft = *(const float2*)(NPc + cg);
    float2 st = *(const float2*)(NPc + 128 + cg);
    float2 agg = make_float2(0.f, 0.f);

#pragma unroll
    for (int r = 0; r < 8; r++) {
        const int tn = tgt_s[w][r];
        if (tn != cur) {  // warp-uniform branch
            red2(g_agg + (size_t)cur * 64 + cg, agg.x, agg.y);
            cur = tn;
            NPc = g_NP + (size_t)cur * 256;
            ft = *(const float2*)(NPc + cg);
            st = *(const float2*)(NPc + 128 + cg);
            agg.x = 0.f; agg.y = 0.f;
        }
        float2 g = unpack2(accG[r]);
        float2 cp = unpack2(accC[r]);
        g.x += bg.x + ft.x + fs[r].x;    g.y += bg.y + ft.y + fs[r].y;
        cp.x += bc.x + st.x + ss[r].x;   cp.y += bc.y + st.y + ss[r].y;
        agg.x += sigmoidf_(g.x) * softplusf_(cp.x);
        agg.y += sigmoidf_(g.y) * softplusf_(cp.y);
    }
    red2(g_agg + (size_t)cur * 64 + cg, agg.x, agg.y);
}

// ---------------- residual + BN statistics (+ agg re-zero) ------------------
__global__ void __launch_bounds__(256) resid_stats(int layer) {
    const int col = threadIdx.x & 63;
    const int rgrp = threadIdx.x >> 6;
    float s = 0.f, q = 0.f;
    for (int row = blockIdx.x * 4 + rgrp; row < N_NODES; row += gridDim.x * 4) {
        const int idx = row * 64 + col;
        float t = g_h[idx] + g_agg[idx];
        g_h[idx] = t;
        g_agg[idx] = 0.f;                    // ready for next layer / replay
        s += t; q += t * t;
    }
    atomicAdd(&g_stats[layer * 128 + col], s);
    atomicAdd(&g_stats[layer * 128 + 64 + col], q);
}

// ---------------- BN normalize (+relu); final: zero deg ---------------------
__global__ void __launch_bounds__(256) bn_kernel(const float* __restrict__ gamma,
                                                 const float* __restrict__ beta,
                                                 int layer, float* __restrict__ dst,
                                                 int do_relu, int final_) {
    const int i = blockIdx.x * blockDim.x + threadIdx.x;  // exact grid: 3.2M
    const int col = i & 63;
    const float invN = 1.f / (float)N_NODES;
    float mean = g_stats[layer * 128 + col] * invN;
    float var = g_stats[layer * 128 + 64 + col] * invN - mean * mean;
    float inv = rsqrtf(var + 1e-5f);
    float v = (g_h[i] - mean) * inv * gamma[layer * 64 + col] + beta[layer * 64 + col];
    if (do_relu) v = fmaxf(v, 0.f);
    dst[i] = v;
    if (final_ && i < N_NODES) g_deg[i] = 0;
}

// ---------------- launch ----------------------------------------------------
extern "C" void kernel_launch(void* const* d_in, const int* in_sizes, int n_in,
                              void* d_out, int out_size) {
    const float* x   = (const float*)d_in[0];
    const float* ea  = (const float*)d_in[1];
    const void*  ei  = d_in[2];
    const float* W1  = (const float*)d_in[3];
    const float* b1  = (const float*)d_in[4];
    const float* W2  = (const float*)d_in[5];
    const float* b2  = (const float*)d_in[6];
    const float* Wf  = (const float*)d_in[7];
    const float* bf  = (const float*)d_in[8];
    const float* Ws  = (const float*)d_in[9];
    const float* bs  = (const float*)d_in[10];
    const float* gamma = (const float*)d_in[11];
    const float* beta  = (const float*)d_in[12];
    float* out = (float*)d_out;

    void *ph, *pwn;
    cudaGetSymbolAddress(&ph, g_h);
    cudaGetSymbolAddress(&pwn, g_Wnode);
    float* hbuf  = (float*)ph;
    float* wnode = (float*)pwn;

    convert_hist<<<(N_EDGES + 255) / 256, 256>>>(ei);
    scan_combine<<<1, 512>>>(Wf, bf, Ws, bs, W2, b2, W1, b1);
    scatter_permute<<<N_EDGES / 256, 256>>>(ea);
    h0_gemm<<<N_NODES / 8, 32>>>(x, W1, b1);
    np0_gemm<<<N_NODES / 8, 64>>>(x);

    for (int l = 0; l < 3; l++) {
        if (l > 0) np_gemm<<<N_NODES / 8, 64>>>(hbuf, wnode + l * 16384);
        edge_kernel<<<N_EDGES / 32, 128>>>(l);
        resid_stats<<<1024, 256>>>(l);
        const int last = (l == 2);
        bn_kernel<<<(N_NODES * 64) / 256, 256>>>(gamma, beta, l,
                                                 last ? out : hbuf,
                                                 last ? 0 : 1, last);
    }
}

// round 15
// speedup vs baseline: 1.1497x; 1.1410x over previous
#include <cuda_runtime.h>
#include <cuda_bf16.h>
#include <cstdint>

#define N_NODES 50000
#define N_EDGES 800000

typedef unsigned long long ull;

// ---------------- scratch (device globals; zero-init at load) ---------------
__device__ float g_h[N_NODES * 64];
__device__ float g_NP[N_NODES * 256];      // parts: [f_t|f_s|s_t|s_s]
__device__ float g_agg[N_NODES * 64];      // kept zeroed
__device__ float g_Wcomb[41 * 384];
__device__ float g_bcomb[384];
__device__ float g_Wnode[3 * 64 * 256];
__device__ float g_W1n[92 * 256];
__device__ float g_b1n[256];
__device__ float g_stats[3 * 128];
// CSR
__device__ int   g_src32[N_EDGES];
__device__ int   g_tgt32[N_EDGES];
__device__ int   g_deg[N_NODES];           // kept zeroed
__device__ int   g_cursor[N_NODES];
__device__ int   g_srcperm[N_EDGES];
__device__ int   g_tgtperm[N_EDGES];
// bf16 hi/lo edge features, sorted order: [edge][24 u32] = 48 bf16 (k 41..47 = 0)
__device__ uint32_t g_eaH[(size_t)N_EDGES * 24];
__device__ uint32_t g_eaL[(size_t)N_EDGES * 24];
// bf16 hi/lo weights: [layer][128 cols][24 u32] (k-contiguous per output col)
__device__ uint32_t g_WH[3 * 128 * 24];
__device__ uint32_t g_WL[3 * 128 * 24];

// ---------------- helpers ----------------------------------------------------
__device__ __forceinline__ ull fma2(ull a, ull b, ull c) {
    ull d;
    asm("fma.rn.f32x2 %0, %1, %2, %3;" : "=l"(d) : "l"(a), "l"(b), "l"(c));
    return d;
}
__device__ __forceinline__ ull dup2(float v) {
    ull d; unsigned u = __float_as_uint(v);
    asm("mov.b64 %0, {%1, %2};" : "=l"(d) : "r"(u), "r"(u));
    return d;
}
__device__ __forceinline__ float2 unpack2(ull v) {
    unsigned lo, hi;
    asm("mov.b64 {%0, %1}, %2;" : "=r"(lo), "=r"(hi) : "l"(v));
    return make_float2(__uint_as_float(lo), __uint_as_float(hi));
}
__device__ __forceinline__ void red2(float* p, float a, float b) {
    asm volatile("red.global.add.v2.f32 [%0], {%1, %2};" :: "l"(p), "f"(a), "f"(b) : "memory");
}
__device__ __forceinline__ float sigmoidf_(float x) {
    return __fdividef(1.f, 1.f + __expf(-x));
}
__device__ __forceinline__ float softplusf_(float x) {
    return fmaxf(x, 0.f) + __logf(1.f + __expf(-fabsf(x)));
}
__device__ __forceinline__ void mma_bf16(float* d, const uint32_t* a, const uint32_t* b) {
    asm volatile(
        "mma.sync.aligned.m16n8k16.row.col.f32.bf16.bf16.f32 "
        "{%0,%1,%2,%3}, {%4,%5,%6,%7}, {%8,%9}, {%0,%1,%2,%3};"
        : "+f"(d[0]), "+f"(d[1]), "+f"(d[2]), "+f"(d[3])
        : "r"(a[0]), "r"(a[1]), "r"(a[2]), "r"(a[3]), "r"(b[0]), "r"(b[1]));
}
__device__ __forceinline__ uint32_t pack_bf16x2(float v0, float v1) {
    unsigned short u0 = __bfloat16_as_ushort(__float2bfloat16(v0));
    unsigned short u1 = __bfloat16_as_ushort(__float2bfloat16(v1));
    return (uint32_t)u0 | ((uint32_t)u1 << 16);
}
__device__ __forceinline__ uint32_t pack_bf16x2_lo(float v0, float v1) {
    __nv_bfloat16 h0 = __float2bfloat16(v0), h1 = __float2bfloat16(v1);
    float l0 = v0 - __bfloat162float(h0), l1 = v1 - __bfloat162float(h1);
    unsigned short u0 = __bfloat16_as_ushort(__float2bfloat16(l0));
    unsigned short u1 = __bfloat16_as_ushort(__float2bfloat16(l1));
    return (uint32_t)u0 | ((uint32_t)u1 << 16);
}

// ---------------- launch 1: convert + histogram + zero stats ----------------
__global__ void __launch_bounds__(256) convert_hist(const void* __restrict__ raw) {
    __shared__ int s_is64;
    const int gt = blockIdx.x * 256 + threadIdx.x;
    if (gt < 3 * 128) g_stats[gt] = 0.f;
    if (threadIdx.x == 0) {
        const int* r32 = (const int*)raw;
        int is64 = 1;
        for (int i = 0; i < 64; i++)
            if (r32[2 * i + 1] != 0) { is64 = 0; break; }
        s_is64 = is64;
    }
    __syncthreads();
    const int e = gt;
    if (e >= N_EDGES) return;
    int s, t;
    if (s_is64) {
        s = (int)((const long long*)raw)[e];
        t = (int)((const long long*)raw)[N_EDGES + e];
    } else {
        s = ((const int*)raw)[e];
        t = ((const int*)raw)[N_EDGES + e];
    }
    s = min(max(s, 0), N_NODES - 1);
    t = min(max(t, 0), N_NODES - 1);
    g_src32[e] = s;
    g_tgt32[e] = t;
    atomicAdd(&g_deg[t], 1);
}

// ---------------- launch 2: scan + weight precombination --------------------
__global__ void __launch_bounds__(512) scan_combine(
    const float* __restrict__ Wf, const float* __restrict__ bf,
    const float* __restrict__ Ws, const float* __restrict__ bs,
    const float* __restrict__ W2, const float* __restrict__ b2,
    const float* __restrict__ W1, const float* __restrict__ b1) {
    __shared__ int ssum[512];
    const int tid = threadIdx.x;

    const int base = tid * 98;
    const int lim = min(base + 98, N_NODES);
    int s = 0;
    for (int i = base; i < lim; i++) s += g_deg[i];
    ssum[tid] = s;
    __syncthreads();
    for (int off = 1; off < 512; off <<= 1) {
        int v = (tid >= off) ? ssum[tid - off] : 0;
        __syncthreads();
        ssum[tid] += v;
        __syncthreads();
    }
    int run = ssum[tid] - s;
    for (int i = base; i < lim; i++) {
        g_cursor[i] = run;
        run += g_deg[i];
    }

    if (tid < 384) {
        const int c = tid;
        const int i = c >> 7;
        const int r = c & 127;
        const bool isF = r < 64;
        const int j = r & 63;
        const float* WB = isF ? Wf : Ws;
        const float* bB = isF ? bf : bs;
        float wc[64];
#pragma unroll
        for (int k = 0; k < 64; k++) wc[k] = WB[i * 12288 + (128 + k) * 64 + j];
        float bacc = bB[i * 64 + j];
#pragma unroll
        for (int k = 0; k < 64; k++) bacc += b2[k] * wc[k];
        g_bcomb[c] = bacc;
        for (int a = 0; a < 41; a++) {
            float acc = 0.f;
#pragma unroll
            for (int k = 0; k < 64; k++) acc += W2[a * 64 + k] * wc[k];
            g_Wcomb[a * 384 + c] = acc;
        }
    }
    // Wnode part layout
    for (int idx = tid; idx < 3 * 64 * 256; idx += 512) {
        int l = idx >> 14;
        int rem = idx & 16383;
        int k = rem >> 8;
        int cc = rem & 255;
        int part = cc >> 6;
        int jj = cc & 63;
        const float* S = (part < 2) ? Wf : Ws;
        int row = k + ((part & 1) ? 64 : 0);
        g_Wnode[idx] = S[l * 12288 + row * 64 + jj];
    }
    __syncthreads();

    // bf16 hi/lo weight tiles: [lay][m 0..127][ku 0..23], k-pair per u32
    for (int idx = tid; idx < 3 * 128 * 24; idx += 512) {
        int lay = idx / 3072;
        int rem = idx % 3072;
        int m = rem / 24;
        int ku = rem % 24;
        int k0 = 2 * ku, k1 = 2 * ku + 1;
        float v0 = (k0 < 41) ? g_Wcomb[k0 * 384 + lay * 128 + m] : 0.f;
        float v1 = (k1 < 41) ? g_Wcomb[k1 * 384 + lay * 128 + m] : 0.f;
        g_WH[idx] = pack_bf16x2(v0, v1);
        g_WL[idx] = pack_bf16x2_lo(v0, v1);
    }
    // W1n = W1 @ Wnode0
    for (int idx = tid; idx < 92 * 256; idx += 512) {
        int a = idx >> 8, cc = idx & 255;
        float acc = 0.f;
#pragma unroll 8
        for (int k = 0; k < 64; k++) acc += W1[a * 64 + k] * g_Wnode[k * 256 + cc];
        g_W1n[idx] = acc;
    }
    if (tid < 256) {
        float acc = 0.f;
#pragma unroll 8
        for (int k = 0; k < 64; k++) acc += b1[k] * g_Wnode[k * 256 + tid];
        g_b1n[tid] = acc;
    }
}

// ---------------- launch 3: scatter + bf16 hi/lo split ----------------------
__global__ void __launch_bounds__(256) scatter_permute(const float* __restrict__ ea) {
    const int w = threadIdx.x >> 5, lane = threadIdx.x & 31;
    const int eb = blockIdx.x * 256 + w * 32;
    const int e = eb + lane;
    const int tg = g_tgt32[e];
    const int pos = atomicAdd(&g_cursor[tg], 1);
    g_srcperm[pos] = g_src32[e];
    g_tgtperm[pos] = tg;
#pragma unroll 4
    for (int j = 0; j < 32; j++) {
        int pe = __shfl_sync(0xffffffffu, pos, j);
        const float* s = ea + (size_t)(eb + j) * 41;
        if (lane < 24) {
            int k0 = 2 * lane, k1 = 2 * lane + 1;
            float v0 = (k0 < 41) ? s[k0] : 0.f;
            float v1 = (k1 < 41) ? s[k1] : 0.f;
            g_eaH[(size_t)pe * 24 + lane] = pack_bf16x2(v0, v1);
            g_eaL[(size_t)pe * 24 + lane] = pack_bf16x2_lo(v0, v1);
        }
    }
}

// ---------------- h0 = x @ W1 + b1 ------------------------------------------
__global__ void __launch_bounds__(32) h0_gemm(const float* __restrict__ x,
                                              const float* __restrict__ W1,
                                              const float* __restrict__ b1) {
    __shared__ __align__(16) ull a_s[8][92];
    const int tid = threadIdx.x;
    const int row0 = blockIdx.x * 8;
    for (int idx = tid; idx < 8 * 92; idx += 32) {
        int r = idx / 92, k = idx - r * 92;
        a_s[r][k] = dup2(x[(size_t)row0 * 92 + idx]);
    }
    __syncwarp();
    const int c = tid * 2;
    ull acc[8];
#pragma unroll
    for (int r = 0; r < 8; r++) acc[r] = 0ull;
#pragma unroll 2
    for (int kk = 0; kk < 46; kk++) {
        ull w0 = *(const ull*)(W1 + (2 * kk) * 64 + c);
        ull w1v = *(const ull*)(W1 + (2 * kk + 1) * 64 + c);
#pragma unroll
        for (int r = 0; r < 8; r++) {
            ulonglong2 av = *(const ulonglong2*)&a_s[r][2 * kk];
            acc[r] = fma2(w0, av.x, acc[r]);
            acc[r] = fma2(w1v, av.y, acc[r]);
        }
    }
    float2 b = *(const float2*)(b1 + c);
#pragma unroll
    for (int r = 0; r < 8; r++) {
        float2 v = unpack2(acc[r]);
        v.x += b.x; v.y += b.y;
        *(float2*)&g_h[(size_t)(row0 + r) * 64 + c] = v;
    }
}

// ---------------- NP0 = x @ W1n + b1n ---------------------------------------
__global__ void __launch_bounds__(64) np0_gemm(const float* __restrict__ x) {
    __shared__ __align__(16) ull b_s[8][92];
    const int tid = threadIdx.x;
    const int row0 = blockIdx.x * 8;
    for (int idx = tid; idx < 8 * 92; idx += 64) {
        int r = idx / 92, k = idx - r * 92;
        b_s[r][k] = dup2(x[(size_t)row0 * 92 + idx]);
    }
    __syncthreads();
    const int c = tid * 4;
    ull acc0[8], acc1[8];
#pragma unroll
    for (int r = 0; r < 8; r++) { acc0[r] = 0ull; acc1[r] = 0ull; }
#pragma unroll 2
    for (int kk = 0; kk < 46; kk++) {
        ulonglong2 w0 = *(const ulonglong2*)(g_W1n + (2 * kk) * 256 + c);
        ulonglong2 w1 = *(const ulonglong2*)(g_W1n + (2 * kk + 1) * 256 + c);
#pragma unroll
        for (int r = 0; r < 8; r++) {
            ulonglong2 av = *(const ulonglong2*)&b_s[r][2 * kk];
            acc0[r] = fma2(w0.x, av.x, acc0[r]);
            acc1[r] = fma2(w0.y, av.x, acc1[r]);
            acc0[r] = fma2(w1.x, av.y, acc0[r]);
            acc1[r] = fma2(w1.y, av.y, acc1[r]);
        }
    }
    float2 ba = *(const float2*)(g_b1n + c);
    float2 bb = *(const float2*)(g_b1n + c + 2);
#pragma unroll
    for (int r = 0; r < 8; r++) {
        float2 v0 = unpack2(acc0[r]);
        float2 v1 = unpack2(acc1[r]);
        float4 o = make_float4(v0.x + ba.x, v0.y + ba.y, v1.x + bb.x, v1.y + bb.y);
        *(float4*)&g_NP[(size_t)(row0 + r) * 256 + c] = o;
    }
}

// ---------------- NP GEMM layers 1,2 ----------------------------------------
__global__ void __launch_bounds__(64) np_gemm(const float* __restrict__ A,
                                              const float* __restrict__ W) {
    __shared__ __align__(16) ull a_s[8][64];
    const int tid = threadIdx.x;
    const int row0 = blockIdx.x * 8;
    for (int idx = tid; idx < 8 * 64; idx += 64) {
        int r = idx >> 6, k = idx & 63;
        a_s[r][k] = dup2(A[(size_t)row0 * 64 + idx]);
    }
    __syncthreads();
    const int c = tid * 4;
    ull acc0[8], acc1[8];
#pragma unroll
    for (int r = 0; r < 8; r++) { acc0[r] = 0ull; acc1[r] = 0ull; }
#pragma unroll 2
    for (int kk = 0; kk < 32; kk++) {
        ulonglong2 w0 = *(const ulonglong2*)(W + (2 * kk) * 256 + c);
        ulonglong2 w1 = *(const ulonglong2*)(W + (2 * kk + 1) * 256 + c);
#pragma unroll
        for (int r = 0; r < 8; r++) {
            ulonglong2 av = *(const ulonglong2*)&a_s[r][2 * kk];
            acc0[r] = fma2(w0.x, av.x, acc0[r]);
            acc1[r] = fma2(w0.y, av.x, acc1[r]);
            acc0[r] = fma2(w1.x, av.y, acc0[r]);
            acc1[r] = fma2(w1.y, av.y, acc1[r]);
        }
    }
#pragma unroll
    for (int r = 0; r < 8; r++) {
        float2 v0 = unpack2(acc0[r]);
        float2 v1 = unpack2(acc1[r]);
        float4 o = make_float4(v0.x, v0.y, v1.x, v1.y);
        *(float4*)&g_NP[(size_t)(row0 + r) * 256 + c] = o;
    }
}

// ---------------- edge kernel: mma.sync HMMA + fused epilogue ---------------
// CTA = 64 edges, 128 threads. Warp w: gate cols [16w,16w+16), core [64+16w,..).
// 3-term bf16 split accumulated in fp32 fragments; raw preacts -> smem pre[64][132];
// then R5-style run-compressed epilogue (16 edges/warp).
__global__ void __launch_bounds__(128) edge_mma(int layer) {
    __shared__ float pre[64 * 132];
    __shared__ int s_tgt[64], s_src[64];
    const int tid = threadIdx.x;
    const int w = tid >> 5, lane = tid & 31;
    const int gid = lane >> 2, tig = lane & 3;
    const int e0 = blockIdx.x * 64;

    if (tid < 64)        s_tgt[tid] = g_tgtperm[e0 + tid];
    else                 s_src[tid - 64] = g_srcperm[e0 + tid - 64];

    const uint32_t* WH = g_WH + layer * 3072;
    const uint32_t* WL = g_WL + layer * 3072;
    const int rG = 16 * w + gid;        // gate output col (A row)
    const int rC = 64 + 16 * w + gid;   // core output col

#pragma unroll
    for (int nh = 0; nh < 2; nh++) {
        float accG[4][4], accC[4][4];
#pragma unroll
        for (int nt = 0; nt < 4; nt++)
#pragma unroll
            for (int i = 0; i < 4; i++) { accG[nt][i] = 0.f; accC[nt][i] = 0.f; }

#pragma unroll
        for (int ks = 0; ks < 3; ks++) {
            const int ku = ks * 8 + tig;
            uint32_t aGh[4] = { WH[rG * 24 + ku],        WH[(rG + 8) * 24 + ku],
                                WH[rG * 24 + ku + 4],    WH[(rG + 8) * 24 + ku + 4] };
            uint32_t aGl[4] = { WL[rG * 24 + ku],        WL[(rG + 8) * 24 + ku],
                                WL[rG * 24 + ku + 4],    WL[(rG + 8) * 24 + ku + 4] };
            uint32_t aCh[4] = { WH[rC * 24 + ku],        WH[(rC + 8) * 24 + ku],
                                WH[rC * 24 + ku + 4],    WH[(rC + 8) * 24 + ku + 4] };
            uint32_t aCl[4] = { WL[rC * 24 + ku],        WL[(rC + 8) * 24 + ku],
                                WL[rC * 24 + ku + 4],    WL[(rC + 8) * 24 + ku + 4] };
#pragma unroll
            for (int nt = 0; nt < 4; nt++) {
                const size_t eg = (size_t)(e0 + nh * 32 + nt * 8 + gid) * 24;
                uint32_t bh[2] = { g_eaH[eg + ku], g_eaH[eg + ku + 4] };
                uint32_t bl[2] = { g_eaL[eg + ku], g_eaL[eg + ku + 4] };
                mma_bf16(accG[nt], aGh, bh);
                mma_bf16(accG[nt], aGh, bl);
                mma_bf16(accG[nt], aGl, bh);
                mma_bf16(accC[nt], aCh, bh);
                mma_bf16(accC[nt], aCh, bl);
                mma_bf16(accC[nt], aCl, bh);
            }
        }
        // store raw preacts: D frag (r, e) -> pre[edge][col]
#pragma unroll
        for (int nt = 0; nt < 4; nt++) {
            const int ce = nh * 32 + nt * 8 + 2 * tig;   // edge of d0/d2
            const int cb = 16 * w + gid;                  // gate col of d0/d1
            pre[ce * 132 + cb]            = accG[nt][0];
            pre[(ce + 1) * 132 + cb]      = accG[nt][1];
            pre[ce * 132 + cb + 8]        = accG[nt][2];
            pre[(ce + 1) * 132 + cb + 8]  = accG[nt][3];
            pre[ce * 132 + 64 + cb]           = accC[nt][0];
            pre[(ce + 1) * 132 + 64 + cb]     = accC[nt][1];
            pre[ce * 132 + 64 + cb + 8]       = accC[nt][2];
            pre[(ce + 1) * 132 + 64 + cb + 8] = accC[nt][3];
        }
    }
    __syncthreads();

    // ---- epilogue: warp w handles edges [16w, 16w+16), lane = col pair -----
    const int cg = 2 * lane;
    const float2 bg = *(const float2*)(g_bcomb + layer * 128 + cg);
    const float2 bc = *(const float2*)(g_bcomb + layer * 128 + 64 + cg);

    int cur = s_tgt[16 * w];
    const float* NPc = g_NP + (size_t)cur * 256;
    float2 ft = *(const float2*)(NPc + cg);
    float2 st = *(const float2*)(NPc + 128 + cg);
    float2 agg = make_float2(0.f, 0.f);

#pragma unroll
    for (int grp = 0; grp < 2; grp++) {
        float2 fs[8], ss[8];
#pragma unroll
        for (int r = 0; r < 8; r++) {
            const float* NPs = g_NP + (size_t)s_src[16 * w + grp * 8 + r] * 256;
            fs[r] = *(const float2*)(NPs + 64 + cg);
            ss[r] = *(const float2*)(NPs + 192 + cg);
        }
#pragma unroll
        for (int r = 0; r < 8; r++) {
            const int le = 16 * w + grp * 8 + r;
            const int tn = s_tgt[le];
            if (tn != cur) {                  // warp-uniform (sorted)
                red2(g_agg + (size_t)cur * 64 + cg, agg.x, agg.y);
                cur = tn;
                NPc = g_NP + (size_t)cur * 256;
                ft = *(const float2*)(NPc + cg);
                st = *(const float2*)(NPc + 128 + cg);
                agg.x = 0.f; agg.y = 0.f;
            }
            float2 g2 = *(const float2*)&pre[le * 132 + cg];
            float2 c2 = *(const float2*)&pre[le * 132 + 64 + cg];
            float gx = g2.x + bg.x + ft.x + fs[r].x;
            float gy = g2.y + bg.y + ft.y + fs[r].y;
            float cx = c2.x + bc.x + st.x + ss[r].x;
            float cy = c2.y + bc.y + st.y + ss[r].y;
            agg.x += sigmoidf_(gx) * softplusf_(cx);
            agg.y += sigmoidf_(gy) * softplusf_(cy);
        }
    }
    red2(g_agg + (size_t)cur * 64 + cg, agg.x, agg.y);
}

// ---------------- residual + BN statistics (+ agg re-zero) ------------------
__global__ void __launch_bounds__(256) resid_stats(int layer) {
    const int col = threadIdx.x & 63;
    const int rgrp = threadIdx.x >> 6;
    float s = 0.f, q = 0.f;
    for (int row = blockIdx.x * 4 + rgrp; row < N_NODES; row += gridDim.x * 4) {
        const int idx = row * 64 + col;
        float t = g_h[idx] + g_agg[idx];
        g_h[idx] = t;
        g_agg[idx] = 0.f;
        s += t; q += t * t;
    }
    atomicAdd(&g_stats[layer * 128 + col], s);
    atomicAdd(&g_stats[layer * 128 + 64 + col], q);
}

// ---------------- BN normalize (+relu); final: zero deg ---------------------
__global__ void __launch_bounds__(256) bn_kernel(const float* __restrict__ gamma,
                                                 const float* __restrict__ beta,
                                                 int layer, float* __restrict__ dst,
                                                 int do_relu, int final_) {
    const int i = blockIdx.x * blockDim.x + threadIdx.x;
    const int col = i & 63;
    const float invN = 1.f / (float)N_NODES;
    float mean = g_stats[layer * 128 + col] * invN;
    float var = g_stats[layer * 128 + 64 + col] * invN - mean * mean;
    float inv = rsqrtf(var + 1e-5f);
    float v = (g_h[i] - mean) * inv * gamma[layer * 64 + col] + beta[layer * 64 + col];
    if (do_relu) v = fmaxf(v, 0.f);
    dst[i] = v;
    if (final_ && i < N_NODES) g_deg[i] = 0;
}

// ---------------- launch ----------------------------------------------------
extern "C" void kernel_launch(void* const* d_in, const int* in_sizes, int n_in,
                              void* d_out, int out_size) {
    const float* x   = (const float*)d_in[0];
    const float* ea  = (const float*)d_in[1];
    const void*  ei  = d_in[2];
    const float* W1  = (const float*)d_in[3];
    const float* b1  = (const float*)d_in[4];
    const float* W2  = (const float*)d_in[5];
    const float* b2  = (const float*)d_in[6];
    const float* Wf  = (const float*)d_in[7];
    const float* bf  = (const float*)d_in[8];
    const float* Ws  = (const float*)d_in[9];
    const float* bs  = (const float*)d_in[10];
    const float* gamma = (const float*)d_in[11];
    const float* beta  = (const float*)d_in[12];
    float* out = (float*)d_out;

    void *ph, *pwn;
    cudaGetSymbolAddress(&ph, g_h);
    cudaGetSymbolAddress(&pwn, g_Wnode);
    float* hbuf  = (float*)ph;
    float* wnode = (float*)pwn;

    convert_hist<<<(N_EDGES + 255) / 256, 256>>>(ei);
    scan_combine<<<1, 512>>>(Wf, bf, Ws, bs, W2, b2, W1, b1);
    scatter_permute<<<N_EDGES / 256, 256>>>(ea);
    h0_gemm<<<N_NODES / 8, 32>>>(x, W1, b1);
    np0_gemm<<<N_NODES / 8, 64>>>(x);

    for (int l = 0; l < 3; l++) {
        if (l > 0) np_gemm<<<N_NODES / 8, 64>>>(hbuf, wnode + l * 16384);
        edge_mma<<<N_EDGES / 64, 128>>>(l);
        resid_stats<<<1024, 256>>>(l);
        const int last = (l == 2);
        bn_kernel<<<(N_NODES * 64) / 256, 256>>>(gamma, beta, l,
                                                 last ? out : hbuf,
                                                 last ? 0 : 1, last);
    }
}

// round 16
// speedup vs baseline: 1.2601x; 1.0960x over previous
#include <cuda_runtime.h>
#include <cuda_bf16.h>
#include <cstdint>

#define N_NODES 50000
#define N_EDGES 800000

typedef unsigned long long ull;

// ---------------- scratch (device globals; zero-init at load) ---------------
__device__ float g_h[N_NODES * 64];
__device__ float g_NP[N_NODES * 256];      // parts: [f_t|f_s|s_t|s_s]
__device__ float g_agg[N_NODES * 64];      // kept zeroed
__device__ float g_Wcomb[41 * 384];
__device__ float g_bcomb[384];
__device__ float g_Wnode[3 * 64 * 256];
__device__ float g_W1n[92 * 256];
__device__ float g_b1n[256];
__device__ float g_stats[3 * 128];
// CSR
__device__ int   g_src32[N_EDGES];
__device__ int   g_tgt32[N_EDGES];
__device__ int   g_deg[N_NODES];           // kept zeroed
__device__ int   g_cursor[N_NODES];
__device__ int   g_srcperm[N_EDGES];
__device__ int   g_tgtperm[N_EDGES];
// bf16 hi/lo edge features, sorted order: [edge][24 u32] = 48 bf16 (k 41..47 = 0)
__device__ uint32_t g_eaH[(size_t)N_EDGES * 24];
__device__ uint32_t g_eaL[(size_t)N_EDGES * 24];
// bf16 hi/lo weights: [layer][128 cols][24 u32] (k-contiguous per output col)
__device__ uint32_t g_WH[3 * 128 * 24];
__device__ uint32_t g_WL[3 * 128 * 24];

// ---------------- helpers ----------------------------------------------------
__device__ __forceinline__ ull fma2(ull a, ull b, ull c) {
    ull d;
    asm("fma.rn.f32x2 %0, %1, %2, %3;" : "=l"(d) : "l"(a), "l"(b), "l"(c));
    return d;
}
__device__ __forceinline__ ull dup2(float v) {
    ull d; unsigned u = __float_as_uint(v);
    asm("mov.b64 %0, {%1, %2};" : "=l"(d) : "r"(u), "r"(u));
    return d;
}
__device__ __forceinline__ float2 unpack2(ull v) {
    unsigned lo, hi;
    asm("mov.b64 {%0, %1}, %2;" : "=r"(lo), "=r"(hi) : "l"(v));
    return make_float2(__uint_as_float(lo), __uint_as_float(hi));
}
__device__ __forceinline__ void red2(float* p, float a, float b) {
    asm volatile("red.global.add.v2.f32 [%0], {%1, %2};" :: "l"(p), "f"(a), "f"(b) : "memory");
}
__device__ __forceinline__ float sigmoidf_(float x) {
    return __fdividef(1.f, 1.f + __expf(-x));
}
__device__ __forceinline__ float softplusf_(float x) {
    return fmaxf(x, 0.f) + __logf(1.f + __expf(-fabsf(x)));
}
__device__ __forceinline__ void mma_bf16(float* d, const uint32_t* a, const uint32_t* b) {
    asm volatile(
        "mma.sync.aligned.m16n8k16.row.col.f32.bf16.bf16.f32 "
        "{%0,%1,%2,%3}, {%4,%5,%6,%7}, {%8,%9}, {%0,%1,%2,%3};"
        : "+f"(d[0]), "+f"(d[1]), "+f"(d[2]), "+f"(d[3])
        : "r"(a[0]), "r"(a[1]), "r"(a[2]), "r"(a[3]), "r"(b[0]), "r"(b[1]));
}
__device__ __forceinline__ uint32_t pack_bf16x2(float v0, float v1) {
    unsigned short u0 = __bfloat16_as_ushort(__float2bfloat16(v0));
    unsigned short u1 = __bfloat16_as_ushort(__float2bfloat16(v1));
    return (uint32_t)u0 | ((uint32_t)u1 << 16);
}
__device__ __forceinline__ uint32_t pack_bf16x2_lo(float v0, float v1) {
    __nv_bfloat16 h0 = __float2bfloat16(v0), h1 = __float2bfloat16(v1);
    float l0 = v0 - __bfloat162float(h0), l1 = v1 - __bfloat162float(h1);
    unsigned short u0 = __bfloat16_as_ushort(__float2bfloat16(l0));
    unsigned short u1 = __bfloat16_as_ushort(__float2bfloat16(l1));
    return (uint32_t)u0 | ((uint32_t)u1 << 16);
}

// ---------------- launch 1: convert + histogram + zero stats ----------------
__global__ void __launch_bounds__(256) convert_hist(const void* __restrict__ raw) {
    __shared__ int s_is64;
    const int gt = blockIdx.x * 256 + threadIdx.x;
    if (gt < 3 * 128) g_stats[gt] = 0.f;
    if (threadIdx.x == 0) {
        const int* r32 = (const int*)raw;
        int is64 = 1;
        for (int i = 0; i < 64; i++)
            if (r32[2 * i + 1] != 0) { is64 = 0; break; }
        s_is64 = is64;
    }
    __syncthreads();
    const int e = gt;
    if (e >= N_EDGES) return;
    int s, t;
    if (s_is64) {
        s = (int)((const long long*)raw)[e];
        t = (int)((const long long*)raw)[N_EDGES + e];
    } else {
        s = ((const int*)raw)[e];
        t = ((const int*)raw)[N_EDGES + e];
    }
    s = min(max(s, 0), N_NODES - 1);
    t = min(max(t, 0), N_NODES - 1);
    g_src32[e] = s;
    g_tgt32[e] = t;
    atomicAdd(&g_deg[t], 1);
}

// ---------------- launch 2: scan + weight precombination --------------------
__global__ void __launch_bounds__(512) scan_combine(
    const float* __restrict__ Wf, const float* __restrict__ bf,
    const float* __restrict__ Ws, const float* __restrict__ bs,
    const float* __restrict__ W2, const float* __restrict__ b2,
    const float* __restrict__ W1, const float* __restrict__ b1) {
    __shared__ int ssum[512];
    const int tid = threadIdx.x;

    const int base = tid * 98;
    const int lim = min(base + 98, N_NODES);
    int s = 0;
    for (int i = base; i < lim; i++) s += g_deg[i];
    ssum[tid] = s;
    __syncthreads();
    for (int off = 1; off < 512; off <<= 1) {
        int v = (tid >= off) ? ssum[tid - off] : 0;
        __syncthreads();
        ssum[tid] += v;
        __syncthreads();
    }
    int run = ssum[tid] - s;
    for (int i = base; i < lim; i++) {
        g_cursor[i] = run;
        run += g_deg[i];
    }

    if (tid < 384) {
        const int c = tid;
        const int i = c >> 7;
        const int r = c & 127;
        const bool isF = r < 64;
        const int j = r & 63;
        const float* WB = isF ? Wf : Ws;
        const float* bB = isF ? bf : bs;
        float wc[64];
#pragma unroll
        for (int k = 0; k < 64; k++) wc[k] = WB[i * 12288 + (128 + k) * 64 + j];
        float bacc = bB[i * 64 + j];
#pragma unroll
        for (int k = 0; k < 64; k++) bacc += b2[k] * wc[k];
        g_bcomb[c] = bacc;
        for (int a = 0; a < 41; a++) {
            float acc = 0.f;
#pragma unroll
            for (int k = 0; k < 64; k++) acc += W2[a * 64 + k] * wc[k];
            g_Wcomb[a * 384 + c] = acc;
        }
    }
    // Wnode part layout
    for (int idx = tid; idx < 3 * 64 * 256; idx += 512) {
        int l = idx >> 14;
        int rem = idx & 16383;
        int k = rem >> 8;
        int cc = rem & 255;
        int part = cc >> 6;
        int jj = cc & 63;
        const float* S = (part < 2) ? Wf : Ws;
        int row = k + ((part & 1) ? 64 : 0);
        g_Wnode[idx] = S[l * 12288 + row * 64 + jj];
    }
    __syncthreads();

    // bf16 hi/lo weight tiles: [lay][m 0..127][ku 0..23], k-pair per u32
    for (int idx = tid; idx < 3 * 128 * 24; idx += 512) {
        int lay = idx / 3072;
        int rem = idx % 3072;
        int m = rem / 24;
        int ku = rem % 24;
        int k0 = 2 * ku, k1 = 2 * ku + 1;
        float v0 = (k0 < 41) ? g_Wcomb[k0 * 384 + lay * 128 + m] : 0.f;
        float v1 = (k1 < 41) ? g_Wcomb[k1 * 384 + lay * 128 + m] : 0.f;
        g_WH[idx] = pack_bf16x2(v0, v1);
        g_WL[idx] = pack_bf16x2_lo(v0, v1);
    }
    // W1n = W1 @ Wnode0
    for (int idx = tid; idx < 92 * 256; idx += 512) {
        int a = idx >> 8, cc = idx & 255;
        float acc = 0.f;
#pragma unroll 8
        for (int k = 0; k < 64; k++) acc += W1[a * 64 + k] * g_Wnode[k * 256 + cc];
        g_W1n[idx] = acc;
    }
    if (tid < 256) {
        float acc = 0.f;
#pragma unroll 8
        for (int k = 0; k < 64; k++) acc += b1[k] * g_Wnode[k * 256 + tid];
        g_b1n[tid] = acc;
    }
}

// ---------------- launch 3: scatter + bf16 hi/lo split ----------------------
__global__ void __launch_bounds__(256) scatter_permute(const float* __restrict__ ea) {
    const int w = threadIdx.x >> 5, lane = threadIdx.x & 31;
    const int eb = blockIdx.x * 256 + w * 32;
    const int e = eb + lane;
    const int tg = g_tgt32[e];
    const int pos = atomicAdd(&g_cursor[tg], 1);
    g_srcperm[pos] = g_src32[e];
    g_tgtperm[pos] = tg;
#pragma unroll 4
    for (int j = 0; j < 32; j++) {
        int pe = __shfl_sync(0xffffffffu, pos, j);
        const float* s = ea + (size_t)(eb + j) * 41;
        if (lane < 24) {
            int k0 = 2 * lane, k1 = 2 * lane + 1;
            float v0 = (k0 < 41) ? s[k0] : 0.f;
            float v1 = (k1 < 41) ? s[k1] : 0.f;
            g_eaH[(size_t)pe * 24 + lane] = pack_bf16x2(v0, v1);
            g_eaL[(size_t)pe * 24 + lane] = pack_bf16x2_lo(v0, v1);
        }
    }
}

// ---------------- h0 = x @ W1 + b1 ------------------------------------------
__global__ void __launch_bounds__(32) h0_gemm(const float* __restrict__ x,
                                              const float* __restrict__ W1,
                                              const float* __restrict__ b1) {
    __shared__ __align__(16) ull a_s[8][92];
    const int tid = threadIdx.x;
    const int row0 = blockIdx.x * 8;
    for (int idx = tid; idx < 8 * 92; idx += 32) {
        int r = idx / 92, k = idx - r * 92;
        a_s[r][k] = dup2(x[(size_t)row0 * 92 + idx]);
    }
    __syncwarp();
    const int c = tid * 2;
    ull acc[8];
#pragma unroll
    for (int r = 0; r < 8; r++) acc[r] = 0ull;
#pragma unroll 2
    for (int kk = 0; kk < 46; kk++) {
        ull w0 = *(const ull*)(W1 + (2 * kk) * 64 + c);
        ull w1v = *(const ull*)(W1 + (2 * kk + 1) * 64 + c);
#pragma unroll
        for (int r = 0; r < 8; r++) {
            ulonglong2 av = *(const ulonglong2*)&a_s[r][2 * kk];
            acc[r] = fma2(w0, av.x, acc[r]);
            acc[r] = fma2(w1v, av.y, acc[r]);
        }
    }
    float2 b = *(const float2*)(b1 + c);
#pragma unroll
    for (int r = 0; r < 8; r++) {
        float2 v = unpack2(acc[r]);
        v.x += b.x; v.y += b.y;
        *(float2*)&g_h[(size_t)(row0 + r) * 64 + c] = v;
    }
}

// ---------------- NP0 = x @ W1n + b1n ---------------------------------------
__global__ void __launch_bounds__(64) np0_gemm(const float* __restrict__ x) {
    __shared__ __align__(16) ull b_s[8][92];
    const int tid = threadIdx.x;
    const int row0 = blockIdx.x * 8;
    for (int idx = tid; idx < 8 * 92; idx += 64) {
        int r = idx / 92, k = idx - r * 92;
        b_s[r][k] = dup2(x[(size_t)row0 * 92 + idx]);
    }
    __syncthreads();
    const int c = tid * 4;
    ull acc0[8], acc1[8];
#pragma unroll
    for (int r = 0; r < 8; r++) { acc0[r] = 0ull; acc1[r] = 0ull; }
#pragma unroll 2
    for (int kk = 0; kk < 46; kk++) {
        ulonglong2 w0 = *(const ulonglong2*)(g_W1n + (2 * kk) * 256 + c);
        ulonglong2 w1 = *(const ulonglong2*)(g_W1n + (2 * kk + 1) * 256 + c);
#pragma unroll
        for (int r = 0; r < 8; r++) {
            ulonglong2 av = *(const ulonglong2*)&b_s[r][2 * kk];
            acc0[r] = fma2(w0.x, av.x, acc0[r]);
            acc1[r] = fma2(w0.y, av.x, acc1[r]);
            acc0[r] = fma2(w1.x, av.y, acc0[r]);
            acc1[r] = fma2(w1.y, av.y, acc1[r]);
        }
    }
    float2 ba = *(const float2*)(g_b1n + c);
    float2 bb = *(const float2*)(g_b1n + c + 2);
#pragma unroll
    for (int r = 0; r < 8; r++) {
        float2 v0 = unpack2(acc0[r]);
        float2 v1 = unpack2(acc1[r]);
        float4 o = make_float4(v0.x + ba.x, v0.y + ba.y, v1.x + bb.x, v1.y + bb.y);
        *(float4*)&g_NP[(size_t)(row0 + r) * 256 + c] = o;
    }
}

// ---------------- NP GEMM layers 1,2 ----------------------------------------
__global__ void __launch_bounds__(64) np_gemm(const float* __restrict__ A,
                                              const float* __restrict__ W) {
    __shared__ __align__(16) ull a_s[8][64];
    const int tid = threadIdx.x;
    const int row0 = blockIdx.x * 8;
    for (int idx = tid; idx < 8 * 64; idx += 64) {
        int r = idx >> 6, k = idx & 63;
        a_s[r][k] = dup2(A[(size_t)row0 * 64 + idx]);
    }
    __syncthreads();
    const int c = tid * 4;
    ull acc0[8], acc1[8];
#pragma unroll
    for (int r = 0; r < 8; r++) { acc0[r] = 0ull; acc1[r] = 0ull; }
#pragma unroll 2
    for (int kk = 0; kk < 32; kk++) {
        ulonglong2 w0 = *(const ulonglong2*)(W + (2 * kk) * 256 + c);
        ulonglong2 w1 = *(const ulonglong2*)(W + (2 * kk + 1) * 256 + c);
#pragma unroll
        for (int r = 0; r < 8; r++) {
            ulonglong2 av = *(const ulonglong2*)&a_s[r][2 * kk];
            acc0[r] = fma2(w0.x, av.x, acc0[r]);
            acc1[r] = fma2(w0.y, av.x, acc1[r]);
            acc0[r] = fma2(w1.x, av.y, acc0[r]);
            acc1[r] = fma2(w1.y, av.y, acc1[r]);
        }
    }
#pragma unroll
    for (int r = 0; r < 8; r++) {
        float2 v0 = unpack2(acc0[r]);
        float2 v1 = unpack2(acc1[r]);
        float4 o = make_float4(v0.x, v0.y, v1.x, v1.y);
        *(float4*)&g_NP[(size_t)(row0 + r) * 256 + c] = o;
    }
}

// ---------------- edge kernel: HMMA with smem-staged B fragments ------------
// CTA = 64 edges, 128 threads. ea staged via coalesced uint4 into stride-28
// rows (112B, 16B-aligned; gid*28 mod 32 all distinct -> conflict-free LDS).
__global__ void __launch_bounds__(128) edge_mma(int layer) {
    __shared__ uint32_t ea_s[2][64][28];
    __shared__ float pre[64 * 132];
    __shared__ int s_tgt[64], s_src[64];
    const int tid = threadIdx.x;
    const int w = tid >> 5, lane = tid & 31;
    const int gid = lane >> 2, tig = lane & 3;
    const int e0 = blockIdx.x * 64;

    // coalesced staging: 64 edges x 6 uint4 per array
    for (int i = tid; i < 64 * 6; i += 128) {
        int r = i / 6, j = i - r * 6;
        uint4 vh = *(const uint4*)(g_eaH + (size_t)(e0 + r) * 24 + 4 * j);
        uint4 vl = *(const uint4*)(g_eaL + (size_t)(e0 + r) * 24 + 4 * j);
        *(uint4*)&ea_s[0][r][4 * j] = vh;
        *(uint4*)&ea_s[1][r][4 * j] = vl;
    }
    if (tid < 64)        s_tgt[tid] = g_tgtperm[e0 + tid];
    else                 s_src[tid - 64] = g_srcperm[e0 + tid - 64];
    __syncthreads();

    const uint32_t* WH = g_WH + layer * 3072;
    const uint32_t* WL = g_WL + layer * 3072;
    const int rG = 16 * w + gid;        // gate output col (A row)
    const int rC = 64 + 16 * w + gid;   // core output col

#pragma unroll
    for (int nh = 0; nh < 2; nh++) {
        float accG[4][4], accC[4][4];
#pragma unroll
        for (int nt = 0; nt < 4; nt++)
#pragma unroll
            for (int i = 0; i < 4; i++) { accG[nt][i] = 0.f; accC[nt][i] = 0.f; }

#pragma unroll
        for (int ks = 0; ks < 3; ks++) {
            const int ku = ks * 8 + tig;
            uint32_t aGh[4] = { WH[rG * 24 + ku],        WH[(rG + 8) * 24 + ku],
                                WH[rG * 24 + ku + 4],    WH[(rG + 8) * 24 + ku + 4] };
            uint32_t aGl[4] = { WL[rG * 24 + ku],        WL[(rG + 8) * 24 + ku],
                                WL[rG * 24 + ku + 4],    WL[(rG + 8) * 24 + ku + 4] };
            uint32_t aCh[4] = { WH[rC * 24 + ku],        WH[(rC + 8) * 24 + ku],
                                WH[rC * 24 + ku + 4],    WH[(rC + 8) * 24 + ku + 4] };
            uint32_t aCl[4] = { WL[rC * 24 + ku],        WL[(rC + 8) * 24 + ku],
                                WL[rC * 24 + ku + 4],    WL[(rC + 8) * 24 + ku + 4] };
#pragma unroll
            for (int nt = 0; nt < 4; nt++) {
                const int le = nh * 32 + nt * 8 + gid;
                uint32_t bh[2] = { ea_s[0][le][ku], ea_s[0][le][ku + 4] };
                uint32_t bl[2] = { ea_s[1][le][ku], ea_s[1][le][ku + 4] };
                mma_bf16(accG[nt], aGh, bh);
                mma_bf16(accG[nt], aGh, bl);
                mma_bf16(accG[nt], aGl, bh);
                mma_bf16(accC[nt], aCh, bh);
                mma_bf16(accC[nt], aCh, bl);
                mma_bf16(accC[nt], aCl, bh);
            }
        }
        // store raw preacts: D frag (r, e) -> pre[edge][col]
#pragma unroll
        for (int nt = 0; nt < 4; nt++) {
            const int ce = nh * 32 + nt * 8 + 2 * tig;   // edge of d0/d2
            const int cb = 16 * w + gid;                  // gate col of d0/d1
            pre[ce * 132 + cb]            = accG[nt][0];
            pre[(ce + 1) * 132 + cb]      = accG[nt][1];
            pre[ce * 132 + cb + 8]        = accG[nt][2];
            pre[(ce + 1) * 132 + cb + 8]  = accG[nt][3];
            pre[ce * 132 + 64 + cb]           = accC[nt][0];
            pre[(ce + 1) * 132 + 64 + cb]     = accC[nt][1];
            pre[ce * 132 + 64 + cb + 8]       = accC[nt][2];
            pre[(ce + 1) * 132 + 64 + cb + 8] = accC[nt][3];
        }
    }
    __syncthreads();

    // ---- epilogue: warp w handles edges [16w, 16w+16), lane = col pair -----
    const int cg = 2 * lane;
    const float2 bg = *(const float2*)(g_bcomb + layer * 128 + cg);
    const float2 bc = *(const float2*)(g_bcomb + layer * 128 + 64 + cg);

    int cur = s_tgt[16 * w];
    const float* NPc = g_NP + (size_t)cur * 256;
    float2 ft = *(const float2*)(NPc + cg);
    float2 st = *(const float2*)(NPc + 128 + cg);
    float2 agg = make_float2(0.f, 0.f);

#pragma unroll
    for (int grp = 0; grp < 2; grp++) {
        float2 fs[8], ss[8];
#pragma unroll
        for (int r = 0; r < 8; r++) {
            const float* NPs = g_NP + (size_t)s_src[16 * w + grp * 8 + r] * 256;
            fs[r] = *(const float2*)(NPs + 64 + cg);
            ss[r] = *(const float2*)(NPs + 192 + cg);
        }
#pragma unroll
        for (int r = 0; r < 8; r++) {
            const int le = 16 * w + grp * 8 + r;
            const int tn = s_tgt[le];
            if (tn != cur) {                  // warp-uniform (sorted)
                red2(g_agg + (size_t)cur * 64 + cg, agg.x, agg.y);
                cur = tn;
                NPc = g_NP + (size_t)cur * 256;
                ft = *(const float2*)(NPc + cg);
                st = *(const float2*)(NPc + 128 + cg);
                agg.x = 0.f; agg.y = 0.f;
            }
            float2 g2 = *(const float2*)&pre[le * 132 + cg];
            float2 c2 = *(const float2*)&pre[le * 132 + 64 + cg];
            float gx = g2.x + bg.x + ft.x + fs[r].x;
            float gy = g2.y + bg.y + ft.y + fs[r].y;
            float cx = c2.x + bc.x + st.x + ss[r].x;
            float cy = c2.y + bc.y + st.y + ss[r].y;
            agg.x += sigmoidf_(gx) * softplusf_(cx);
            agg.y += sigmoidf_(gy) * softplusf_(cy);
        }
    }
    red2(g_agg + (size_t)cur * 64 + cg, agg.x, agg.y);
}

// ---------------- residual + BN statistics (+ agg re-zero) ------------------
__global__ void __launch_bounds__(256) resid_stats(int layer) {
    const int col = threadIdx.x & 63;
    const int rgrp = threadIdx.x >> 6;
    float s = 0.f, q = 0.f;
    for (int row = blockIdx.x * 4 + rgrp; row < N_NODES; row += gridDim.x * 4) {
        const int idx = row * 64 + col;
        float t = g_h[idx] + g_agg[idx];
        g_h[idx] = t;
        g_agg[idx] = 0.f;
        s += t; q += t * t;
    }
    atomicAdd(&g_stats[layer * 128 + col], s);
    atomicAdd(&g_stats[layer * 128 + 64 + col], q);
}

// ---------------- BN normalize (+relu); final: zero deg ---------------------
__global__ void __launch_bounds__(256) bn_kernel(const float* __restrict__ gamma,
                                                 const float* __restrict__ beta,
                                                 int layer, float* __restrict__ dst,
                                                 int do_relu, int final_) {
    const int i = blockIdx.x * blockDim.x + threadIdx.x;
    const int col = i & 63;
    const float invN = 1.f / (float)N_NODES;
    float mean = g_stats[layer * 128 + col] * invN;
    float var = g_stats[layer * 128 + 64 + col] * invN - mean * mean;
    float inv = rsqrtf(var + 1e-5f);
    float v = (g_h[i] - mean) * inv * gamma[layer * 64 + col] + beta[layer * 64 + col];
    if (do_relu) v = fmaxf(v, 0.f);
    dst[i] = v;
    if (final_ && i < N_NODES) g_deg[i] = 0;
}

// ---------------- launch ----------------------------------------------------
extern "C" void kernel_launch(void* const* d_in, const int* in_sizes, int n_in,
                              void* d_out, int out_size) {
    const float* x   = (const float*)d_in[0];
    const float* ea  = (const float*)d_in[1];
    const void*  ei  = d_in[2];
    const float* W1  = (const float*)d_in[3];
    const float* b1  = (const float*)d_in[4];
    const float* W2  = (const float*)d_in[5];
    const float* b2  = (const float*)d_in[6];
    const float* Wf  = (const float*)d_in[7];
    const float* bf  = (const float*)d_in[8];
    const float* Ws  = (const float*)d_in[9];
    const float* bs  = (const float*)d_in[10];
    const float* gamma = (const float*)d_in[11];
    const float* beta  = (const float*)d_in[12];
    float* out = (float*)d_out;

    void *ph, *pwn;
    cudaGetSymbolAddress(&ph, g_h);
    cudaGetSymbolAddress(&pwn, g_Wnode);
    float* hbuf  = (float*)ph;
    float* wnode = (float*)pwn;

    convert_hist<<<(N_EDGES + 255) / 256, 256>>>(ei);
    scan_combine<<<1, 512>>>(Wf, bf, Ws, bs, W2, b2, W1, b1);
    scatter_permute<<<N_EDGES / 256, 256>>>(ea);
    h0_gemm<<<N_NODES / 8, 32>>>(x, W1, b1);
    np0_gemm<<<N_NODES / 8, 64>>>(x);

    for (int l = 0; l < 3; l++) {
        if (l > 0) np_gemm<<<N_NODES / 8, 64>>>(hbuf, wnode + l * 16384);
        edge_mma<<<N_EDGES / 64, 128>>>(l);
        resid_stats<<<1024, 256>>>(l);
        const int last = (l == 2);
        bn_kernel<<<(N_NODES * 64) / 256, 256>>>(gamma, beta, l,
                                                 last ? out : hbuf,
                                                 last ? 0 : 1, last);
    }
}

// round 17
// speedup vs baseline: 1.2670x; 1.0054x over previous
#include <cuda_runtime.h>
#include <cuda_bf16.h>
#include <cstdint>

#define N_NODES 50000
#define N_EDGES 800000

typedef unsigned long long ull;

// ---------------- scratch (device globals; zero-init at load) ---------------
__device__ float g_h[N_NODES * 64];
__device__ float g_NP[N_NODES * 256];      // parts: [f_t|f_s|s_t|s_s]
__device__ float g_agg[N_NODES * 64];      // kept zeroed
__device__ float g_Wcomb[41 * 384];
__device__ float g_bcomb[384];
__device__ float g_Wnode[3 * 64 * 256];
__device__ float g_W1n[92 * 256];
__device__ float g_b1n[256];
__device__ float g_stats[3 * 128];
// CSR
__device__ int   g_src32[N_EDGES];
__device__ int   g_tgt32[N_EDGES];
__device__ int   g_deg[N_NODES];           // kept zeroed
__device__ int   g_cursor[N_NODES];
__device__ int   g_srcperm[N_EDGES];
__device__ int   g_tgtperm[N_EDGES];
// bf16 hi/lo edge features, sorted order: [edge][24 u32] = 48 bf16 (k 41..47 = 0)
__device__ uint32_t g_eaH[(size_t)N_EDGES * 24];
__device__ uint32_t g_eaL[(size_t)N_EDGES * 24];
// bf16 hi/lo weights: [layer][128 cols][24 u32] (k-contiguous per output col)
__device__ uint32_t g_WH[3 * 128 * 24];
__device__ uint32_t g_WL[3 * 128 * 24];
// pre-packed A fragments in register-load order:
// [lay][warp][ks][mat(Gh,Gl,Ch,Cl)][lane] -> uint4
__device__ __align__(16) uint4 g_Wfrag[3 * 4 * 3 * 4 * 32];

// ---------------- helpers ----------------------------------------------------
__device__ __forceinline__ ull fma2(ull a, ull b, ull c) {
    ull d;
    asm("fma.rn.f32x2 %0, %1, %2, %3;" : "=l"(d) : "l"(a), "l"(b), "l"(c));
    return d;
}
__device__ __forceinline__ ull dup2(float v) {
    ull d; unsigned u = __float_as_uint(v);
    asm("mov.b64 %0, {%1, %2};" : "=l"(d) : "r"(u), "r"(u));
    return d;
}
__device__ __forceinline__ float2 unpack2(ull v) {
    unsigned lo, hi;
    asm("mov.b64 {%0, %1}, %2;" : "=r"(lo), "=r"(hi) : "l"(v));
    return make_float2(__uint_as_float(lo), __uint_as_float(hi));
}
__device__ __forceinline__ void red2(float* p, float a, float b) {
    asm volatile("red.global.add.v2.f32 [%0], {%1, %2};" :: "l"(p), "f"(a), "f"(b) : "memory");
}
__device__ __forceinline__ float sigmoidf_(float x) {
    return __fdividef(1.f, 1.f + __expf(-x));
}
__device__ __forceinline__ float softplusf_(float x) {
    return fmaxf(x, 0.f) + __logf(1.f + __expf(-fabsf(x)));
}
__device__ __forceinline__ void mma_bf16(float* d, const uint4 a, const uint32_t* b) {
    asm volatile(
        "mma.sync.aligned.m16n8k16.row.col.f32.bf16.bf16.f32 "
        "{%0,%1,%2,%3}, {%4,%5,%6,%7}, {%8,%9}, {%0,%1,%2,%3};"
        : "+f"(d[0]), "+f"(d[1]), "+f"(d[2]), "+f"(d[3])
        : "r"(a.x), "r"(a.y), "r"(a.z), "r"(a.w), "r"(b[0]), "r"(b[1]));
}
__device__ __forceinline__ uint32_t pack_bf16x2(float v0, float v1) {
    unsigned short u0 = __bfloat16_as_ushort(__float2bfloat16(v0));
    unsigned short u1 = __bfloat16_as_ushort(__float2bfloat16(v1));
    return (uint32_t)u0 | ((uint32_t)u1 << 16);
}
__device__ __forceinline__ uint32_t pack_bf16x2_lo(float v0, float v1) {
    __nv_bfloat16 h0 = __float2bfloat16(v0), h1 = __float2bfloat16(v1);
    float l0 = v0 - __bfloat162float(h0), l1 = v1 - __bfloat162float(h1);
    unsigned short u0 = __bfloat16_as_ushort(__float2bfloat16(l0));
    unsigned short u1 = __bfloat16_as_ushort(__float2bfloat16(l1));
    return (uint32_t)u0 | ((uint32_t)u1 << 16);
}

// ---------------- launch 1: convert + histogram + zero stats ----------------
__global__ void __launch_bounds__(256) convert_hist(const void* __restrict__ raw) {
    __shared__ int s_is64;
    const int gt = blockIdx.x * 256 + threadIdx.x;
    if (gt < 3 * 128) g_stats[gt] = 0.f;
    if (threadIdx.x == 0) {
        const int* r32 = (const int*)raw;
        int is64 = 1;
        for (int i = 0; i < 64; i++)
            if (r32[2 * i + 1] != 0) { is64 = 0; break; }
        s_is64 = is64;
    }
    __syncthreads();
    const int e = gt;
    if (e >= N_EDGES) return;
    int s, t;
    if (s_is64) {
        s = (int)((const long long*)raw)[e];
        t = (int)((const long long*)raw)[N_EDGES + e];
    } else {
        s = ((const int*)raw)[e];
        t = ((const int*)raw)[N_EDGES + e];
    }
    s = min(max(s, 0), N_NODES - 1);
    t = min(max(t, 0), N_NODES - 1);
    g_src32[e] = s;
    g_tgt32[e] = t;
    atomicAdd(&g_deg[t], 1);
}

// ---------------- launch 2: scan + weight precombination --------------------
__global__ void __launch_bounds__(512) scan_combine(
    const float* __restrict__ Wf, const float* __restrict__ bf,
    const float* __restrict__ Ws, const float* __restrict__ bs,
    const float* __restrict__ W2, const float* __restrict__ b2,
    const float* __restrict__ W1, const float* __restrict__ b1) {
    __shared__ int ssum[512];
    const int tid = threadIdx.x;

    const int base = tid * 98;
    const int lim = min(base + 98, N_NODES);
    int s = 0;
    for (int i = base; i < lim; i++) s += g_deg[i];
    ssum[tid] = s;
    __syncthreads();
    for (int off = 1; off < 512; off <<= 1) {
        int v = (tid >= off) ? ssum[tid - off] : 0;
        __syncthreads();
        ssum[tid] += v;
        __syncthreads();
    }
    int run = ssum[tid] - s;
    for (int i = base; i < lim; i++) {
        g_cursor[i] = run;
        run += g_deg[i];
    }

    if (tid < 384) {
        const int c = tid;
        const int i = c >> 7;
        const int r = c & 127;
        const bool isF = r < 64;
        const int j = r & 63;
        const float* WB = isF ? Wf : Ws;
        const float* bB = isF ? bf : bs;
        float wc[64];
#pragma unroll
        for (int k = 0; k < 64; k++) wc[k] = WB[i * 12288 + (128 + k) * 64 + j];
        float bacc = bB[i * 64 + j];
#pragma unroll
        for (int k = 0; k < 64; k++) bacc += b2[k] * wc[k];
        g_bcomb[c] = bacc;
        for (int a = 0; a < 41; a++) {
            float acc = 0.f;
#pragma unroll
            for (int k = 0; k < 64; k++) acc += W2[a * 64 + k] * wc[k];
            g_Wcomb[a * 384 + c] = acc;
        }
    }
    // Wnode part layout
    for (int idx = tid; idx < 3 * 64 * 256; idx += 512) {
        int l = idx >> 14;
        int rem = idx & 16383;
        int k = rem >> 8;
        int cc = rem & 255;
        int part = cc >> 6;
        int jj = cc & 63;
        const float* S = (part < 2) ? Wf : Ws;
        int row = k + ((part & 1) ? 64 : 0);
        g_Wnode[idx] = S[l * 12288 + row * 64 + jj];
    }
    __syncthreads();

    // bf16 hi/lo weight tiles: [lay][m 0..127][ku 0..23], k-pair per u32
    for (int idx = tid; idx < 3 * 128 * 24; idx += 512) {
        int lay = idx / 3072;
        int rem = idx % 3072;
        int m = rem / 24;
        int ku = rem % 24;
        int k0 = 2 * ku, k1 = 2 * ku + 1;
        float v0 = (k0 < 41) ? g_Wcomb[k0 * 384 + lay * 128 + m] : 0.f;
        float v1 = (k1 < 41) ? g_Wcomb[k1 * 384 + lay * 128 + m] : 0.f;
        g_WH[idx] = pack_bf16x2(v0, v1);
        g_WL[idx] = pack_bf16x2_lo(v0, v1);
    }
    // W1n = W1 @ Wnode0
    for (int idx = tid; idx < 92 * 256; idx += 512) {
        int a = idx >> 8, cc = idx & 255;
        float acc = 0.f;
#pragma unroll 8
        for (int k = 0; k < 64; k++) acc += W1[a * 64 + k] * g_Wnode[k * 256 + cc];
        g_W1n[idx] = acc;
    }
    if (tid < 256) {
        float acc = 0.f;
#pragma unroll 8
        for (int k = 0; k < 64; k++) acc += b1[k] * g_Wnode[k * 256 + tid];
        g_b1n[tid] = acc;
    }
    __syncthreads();

    // pre-packed A fragments: [lay][w][ks][mat][lane] -> uint4
    // mat 0=Gh 1=Gl 2=Ch 3=Cl; lane: gid=lane>>2, tig=lane&3; ku=ks*8+tig
    // frag = { W[r][ku], W[r+8][ku], W[r][ku+4], W[r+8][ku+4] },
    //   r = (mat<2 ? 16w+gid : 64+16w+gid)
    for (int idx = tid; idx < 3 * 4 * 3 * 4 * 32; idx += 512) {
        int lane = idx & 31;
        int rest = idx >> 5;
        int mat = rest & 3; rest >>= 2;
        int ks = rest % 3;  rest /= 3;
        int w = rest & 3;
        int lay = rest >> 2;
        int gid = lane >> 2, tig = lane & 3;
        int ku = ks * 8 + tig;
        int r = ((mat < 2) ? 16 * w + gid : 64 + 16 * w + gid);
        const uint32_t* WB = ((mat & 1) ? g_WL : g_WH) + lay * 3072;
        uint4 f;
        f.x = WB[r * 24 + ku];
        f.y = WB[(r + 8) * 24 + ku];
        f.z = WB[r * 24 + ku + 4];
        f.w = WB[(r + 8) * 24 + ku + 4];
        g_Wfrag[idx] = f;
    }
}

// ---------------- launch 3: scatter + bf16 hi/lo split ----------------------
__global__ void __launch_bounds__(256) scatter_permute(const float* __restrict__ ea) {
    const int w = threadIdx.x >> 5, lane = threadIdx.x & 31;
    const int eb = blockIdx.x * 256 + w * 32;
    const int e = eb + lane;
    const int tg = g_tgt32[e];
    const int pos = atomicAdd(&g_cursor[tg], 1);
    g_srcperm[pos] = g_src32[e];
    g_tgtperm[pos] = tg;
#pragma unroll 4
    for (int j = 0; j < 32; j++) {
        int pe = __shfl_sync(0xffffffffu, pos, j);
        const float* s = ea + (size_t)(eb + j) * 41;
        if (lane < 24) {
            int k0 = 2 * lane, k1 = 2 * lane + 1;
            float v0 = (k0 < 41) ? s[k0] : 0.f;
            float v1 = (k1 < 41) ? s[k1] : 0.f;
            g_eaH[(size_t)pe * 24 + lane] = pack_bf16x2(v0, v1);
            g_eaL[(size_t)pe * 24 + lane] = pack_bf16x2_lo(v0, v1);
        }
    }
}

// ---------------- h0 = x @ W1 + b1 ------------------------------------------
__global__ void __launch_bounds__(32) h0_gemm(const float* __restrict__ x,
                                              const float* __restrict__ W1,
                                              const float* __restrict__ b1) {
    __shared__ __align__(16) ull a_s[8][92];
    const int tid = threadIdx.x;
    const int row0 = blockIdx.x * 8;
    for (int idx = tid; idx < 8 * 92; idx += 32) {
        int r = idx / 92, k = idx - r * 92;
        a_s[r][k] = dup2(x[(size_t)row0 * 92 + idx]);
    }
    __syncwarp();
    const int c = tid * 2;
    ull acc[8];
#pragma unroll
    for (int r = 0; r < 8; r++) acc[r] = 0ull;
#pragma unroll 2
    for (int kk = 0; kk < 46; kk++) {
        ull w0 = *(const ull*)(W1 + (2 * kk) * 64 + c);
        ull w1v = *(const ull*)(W1 + (2 * kk + 1) * 64 + c);
#pragma unroll
        for (int r = 0; r < 8; r++) {
            ulonglong2 av = *(const ulonglong2*)&a_s[r][2 * kk];
            acc[r] = fma2(w0, av.x, acc[r]);
            acc[r] = fma2(w1v, av.y, acc[r]);
        }
    }
    float2 b = *(const float2*)(b1 + c);
#pragma unroll
    for (int r = 0; r < 8; r++) {
        float2 v = unpack2(acc[r]);
        v.x += b.x; v.y += b.y;
        *(float2*)&g_h[(size_t)(row0 + r) * 64 + c] = v;
    }
}

// ---------------- NP0 = x @ W1n + b1n ---------------------------------------
__global__ void __launch_bounds__(64) np0_gemm(const float* __restrict__ x) {
    __shared__ __align__(16) ull b_s[8][92];
    const int tid = threadIdx.x;
    const int row0 = blockIdx.x * 8;
    for (int idx = tid; idx < 8 * 92; idx += 64) {
        int r = idx / 92, k = idx - r * 92;
        b_s[r][k] = dup2(x[(size_t)row0 * 92 + idx]);
    }
    __syncthreads();
    const int c = tid * 4;
    ull acc0[8], acc1[8];
#pragma unroll
    for (int r = 0; r < 8; r++) { acc0[r] = 0ull; acc1[r] = 0ull; }
#pragma unroll 2
    for (int kk = 0; kk < 46; kk++) {
        ulonglong2 w0 = *(const ulonglong2*)(g_W1n + (2 * kk) * 256 + c);
        ulonglong2 w1 = *(const ulonglong2*)(g_W1n + (2 * kk + 1) * 256 + c);
#pragma unroll
        for (int r = 0; r < 8; r++) {
            ulonglong2 av = *(const ulonglong2*)&b_s[r][2 * kk];
            acc0[r] = fma2(w0.x, av.x, acc0[r]);
            acc1[r] = fma2(w0.y, av.x, acc1[r]);
            acc0[r] = fma2(w1.x, av.y, acc0[r]);
            acc1[r] = fma2(w1.y, av.y, acc1[r]);
        }
    }
    float2 ba = *(const float2*)(g_b1n + c);
    float2 bb = *(const float2*)(g_b1n + c + 2);
#pragma unroll
    for (int r = 0; r < 8; r++) {
        float2 v0 = unpack2(acc0[r]);
        float2 v1 = unpack2(acc1[r]);
        float4 o = make_float4(v0.x + ba.x, v0.y + ba.y, v1.x + bb.x, v1.y + bb.y);
        *(float4*)&g_NP[(size_t)(row0 + r) * 256 + c] = o;
    }
}

// ---------------- NP GEMM layers 1,2 ----------------------------------------
__global__ void __launch_bounds__(64) np_gemm(const float* __restrict__ A,
                                              const float* __restrict__ W) {
    __shared__ __align__(16) ull a_s[8][64];
    const int tid = threadIdx.x;
    const int row0 = blockIdx.x * 8;
    for (int idx = tid; idx < 8 * 64; idx += 64) {
        int r = idx >> 6, k = idx & 63;
        a_s[r][k] = dup2(A[(size_t)row0 * 64 + idx]);
    }
    __syncthreads();
    const int c = tid * 4;
    ull acc0[8], acc1[8];
#pragma unroll
    for (int r = 0; r < 8; r++) { acc0[r] = 0ull; acc1[r] = 0ull; }
#pragma unroll 2
    for (int kk = 0; kk < 32; kk++) {
        ulonglong2 w0 = *(const ulonglong2*)(W + (2 * kk) * 256 + c);
        ulonglong2 w1 = *(const ulonglong2*)(W + (2 * kk + 1) * 256 + c);
#pragma unroll
        for (int r = 0; r < 8; r++) {
            ulonglong2 av = *(const ulonglong2*)&a_s[r][2 * kk];
            acc0[r] = fma2(w0.x, av.x, acc0[r]);
            acc1[r] = fma2(w0.y, av.x, acc1[r]);
            acc0[r] = fma2(w1.x, av.y, acc0[r]);
            acc1[r] = fma2(w1.y, av.y, acc1[r]);
        }
    }
#pragma unroll
    for (int r = 0; r < 8; r++) {
        float2 v0 = unpack2(acc0[r]);
        float2 v1 = unpack2(acc1[r]);
        float4 o = make_float4(v0.x, v0.y, v1.x, v1.y);
        *(float4*)&g_NP[(size_t)(row0 + r) * 256 + c] = o;
    }
}

// ---------------- edge kernel: HMMA, smem B + coalesced A fragments ---------
__global__ void __launch_bounds__(128) edge_mma(int layer) {
    __shared__ uint32_t ea_s[2][64][28];
    __shared__ float pre[64 * 132];
    __shared__ int s_tgt[64], s_src[64];
    const int tid = threadIdx.x;
    const int w = tid >> 5, lane = tid & 31;
    const int gid = lane >> 2, tig = lane & 3;
    const int e0 = blockIdx.x * 64;

    // coalesced staging: 64 edges x 6 uint4 per array
    for (int i = tid; i < 64 * 6; i += 128) {
        int r = i / 6, j = i - r * 6;
        uint4 vh = *(const uint4*)(g_eaH + (size_t)(e0 + r) * 24 + 4 * j);
        uint4 vl = *(const uint4*)(g_eaL + (size_t)(e0 + r) * 24 + 4 * j);
        *(uint4*)&ea_s[0][r][4 * j] = vh;
        *(uint4*)&ea_s[1][r][4 * j] = vl;
    }
    if (tid < 64)        s_tgt[tid] = g_tgtperm[e0 + tid];
    else                 s_src[tid - 64] = g_srcperm[e0 + tid - 64];
    __syncthreads();

    // coalesced A-fragment base for this (layer, warp)
    const uint4* WF = g_Wfrag + ((size_t)(layer * 4 + w) * 3) * 4 * 32 + lane;

#pragma unroll
    for (int nh = 0; nh < 2; nh++) {
        float accG[4][4], accC[4][4];
#pragma unroll
        for (int nt = 0; nt < 4; nt++)
#pragma unroll
            for (int i = 0; i < 4; i++) { accG[nt][i] = 0.f; accC[nt][i] = 0.f; }

#pragma unroll
        for (int ks = 0; ks < 3; ks++) {
            const int ku = ks * 8 + tig;
            const uint4* WFk = WF + (size_t)ks * 4 * 32;
            uint4 aGh = WFk[0 * 32];
            uint4 aGl = WFk[1 * 32];
            uint4 aCh = WFk[2 * 32];
            uint4 aCl = WFk[3 * 32];
#pragma unroll
            for (int nt = 0; nt < 4; nt++) {
                const int le = nh * 32 + nt * 8 + gid;
                uint32_t bh[2] = { ea_s[0][le][ku], ea_s[0][le][ku + 4] };
                uint32_t bl[2] = { ea_s[1][le][ku], ea_s[1][le][ku + 4] };
                mma_bf16(accG[nt], aGh, bh);
                mma_bf16(accG[nt], aGh, bl);
                mma_bf16(accG[nt], aGl, bh);
                mma_bf16(accC[nt], aCh, bh);
                mma_bf16(accC[nt], aCh, bl);
                mma_bf16(accC[nt], aCl, bh);
            }
        }
        // store raw preacts: D frag (r, e) -> pre[edge][col]
#pragma unroll
        for (int nt = 0; nt < 4; nt++) {
            const int ce = nh * 32 + nt * 8 + 2 * tig;   // edge of d0/d2
            const int cb = 16 * w + gid;                  // gate col of d0/d1
            pre[ce * 132 + cb]            = accG[nt][0];
            pre[(ce + 1) * 132 + cb]      = accG[nt][1];
            pre[ce * 132 + cb + 8]        = accG[nt][2];
            pre[(ce + 1) * 132 + cb + 8]  = accG[nt][3];
            pre[ce * 132 + 64 + cb]           = accC[nt][0];
            pre[(ce + 1) * 132 + 64 + cb]     = accC[nt][1];
            pre[ce * 132 + 64 + cb + 8]       = accC[nt][2];
            pre[(ce + 1) * 132 + 64 + cb + 8] = accC[nt][3];
        }
    }
    __syncthreads();

    // ---- epilogue: warp w handles edges [16w, 16w+16), lane = col pair -----
    const int cg = 2 * lane;
    const float2 bg = *(const float2*)(g_bcomb + layer * 128 + cg);
    const float2 bc = *(const float2*)(g_bcomb + layer * 128 + 64 + cg);

    int cur = s_tgt[16 * w];
    const float* NPc = g_NP + (size_t)cur * 256;
    float2 ft = *(const float2*)(NPc + cg);
    float2 st = *(const float2*)(NPc + 128 + cg);
    float2 agg = make_float2(0.f, 0.f);

#pragma unroll
    for (int grp = 0; grp < 2; grp++) {
        float2 fs[8], ss[8];
#pragma unroll
        for (int r = 0; r < 8; r++) {
            const float* NPs = g_NP + (size_t)s_src[16 * w + grp * 8 + r] * 256;
            fs[r] = *(const float2*)(NPs + 64 + cg);
            ss[r] = *(const float2*)(NPs + 192 + cg);
        }
#pragma unroll
        for (int r = 0; r < 8; r++) {
            const int le = 16 * w + grp * 8 + r;
            const int tn = s_tgt[le];
            if (tn != cur) {                  // warp-uniform (sorted)
                red2(g_agg + (size_t)cur * 64 + cg, agg.x, agg.y);
                cur = tn;
                NPc = g_NP + (size_t)cur * 256;
                ft = *(const float2*)(NPc + cg);
                st = *(const float2*)(NPc + 128 + cg);
                agg.x = 0.f; agg.y = 0.f;
            }
            float2 g2 = *(const float2*)&pre[le * 132 + cg];
            float2 c2 = *(const float2*)&pre[le * 132 + 64 + cg];
            float gx = g2.x + bg.x + ft.x + fs[r].x;
            float gy = g2.y + bg.y + ft.y + fs[r].y;
            float cx = c2.x + bc.x + st.x + ss[r].x;
            float cy = c2.y + bc.y + st.y + ss[r].y;
            agg.x += sigmoidf_(gx) * softplusf_(cx);
            agg.y += sigmoidf_(gy) * softplusf_(cy);
        }
    }
    red2(g_agg + (size_t)cur * 64 + cg, agg.x, agg.y);
}

// ---------------- residual + BN statistics (+ agg re-zero) ------------------
__global__ void __launch_bounds__(256) resid_stats(int layer) {
    const int col = threadIdx.x & 63;
    const int rgrp = threadIdx.x >> 6;
    float s = 0.f, q = 0.f;
    for (int row = blockIdx.x * 4 + rgrp; row < N_NODES; row += gridDim.x * 4) {
        const int idx = row * 64 + col;
        float t = g_h[idx] + g_agg[idx];
        g_h[idx] = t;
        g_agg[idx] = 0.f;
        s += t; q += t * t;
    }
    atomicAdd(&g_stats[layer * 128 + col], s);
    atomicAdd(&g_stats[layer * 128 + 64 + col], q);
}

// ---------------- BN normalize (+relu); final: zero deg ---------------------
__global__ void __launch_bounds__(256) bn_kernel(const float* __restrict__ gamma,
                                                 const float* __restrict__ beta,
                                                 int layer, float* __restrict__ dst,
                                                 int do_relu, int final_) {
    const int i = blockIdx.x * blockDim.x + threadIdx.x;
    const int col = i & 63;
    const float invN = 1.f / (float)N_NODES;
    float mean = g_stats[layer * 128 + col] * invN;
    float var = g_stats[layer * 128 + 64 + col] * invN - mean * mean;
    float inv = rsqrtf(var + 1e-5f);
    float v = (g_h[i] - mean) * inv * gamma[layer * 64 + col] + beta[layer * 64 + col];
    if (do_relu) v = fmaxf(v, 0.f);
    dst[i] = v;
    if (final_ && i < N_NODES) g_deg[i] = 0;
}

// ---------------- launch ----------------------------------------------------
extern "C" void kernel_launch(void* const* d_in, const int* in_sizes, int n_in,
                              void* d_out, int out_size) {
    const float* x   = (const float*)d_in[0];
    const float* ea  = (const float*)d_in[1];
    const void*  ei  = d_in[2];
    const float* W1  = (const float*)d_in[3];
    const float* b1  = (const float*)d_in[4];
    const float* W2  = (const float*)d_in[5];
    const float* b2  = (const float*)d_in[6];
    const float* Wf  = (const float*)d_in[7];
    const float* bf  = (const float*)d_in[8];
    const float* Ws  = (const float*)d_in[9];
    const float* bs  = (const float*)d_in[10];
    const float* gamma = (const float*)d_in[11];
    const float* beta  = (const float*)d_in[12];
    float* out = (float*)d_out;

    void *ph, *pwn;
    cudaGetSymbolAddress(&ph, g_h);
    cudaGetSymbolAddress(&pwn, g_Wnode);
    float* hbuf  = (float*)ph;
    float* wnode = (float*)pwn;

    convert_hist<<<(N_EDGES + 255) / 256, 256>>>(ei);
    scan_combine<<<1, 512>>>(Wf, bf, Ws, bs, W2, b2, W1, b1);
    scatter_permute<<<N_EDGES / 256, 256>>>(ea);
    h0_gemm<<<N_NODES / 8, 32>>>(x, W1, b1);
    np0_gemm<<<N_NODES / 8, 64>>>(x);

    for (int l = 0; l < 3; l++) {
        if (l > 0) np_gemm<<<N_NODES / 8, 64>>>(hbuf, wnode + l * 16384);
        edge_mma<<<N_EDGES / 64, 128>>>(l);
        resid_stats<<<1024, 256>>>(l);
        const int last = (l == 2);
        bn_kernel<<<(N_NODES * 64) / 256, 256>>>(gamma, beta, l,
                                                 last ? out : hbuf,
                                                 last ? 0 : 1, last);
    }
}